// round 15
// baseline (speedup 1.0000x reference)
#include <cuda_runtime.h>
#include <cuda_bf16.h>
#include <math.h>
#include <stdint.h>

#define Dm 512
#define DD (512*512)
typedef __nv_bfloat16 bf;

// ---------------- scratch (device globals; no allocation) ----------------
__device__ __align__(16) float g_seg0[4*1024*512];
__device__ __align__(16) float g_seg1[4*256*512];
__device__ __align__(16) float g_seg2[4*64*512];
__device__ __align__(16) float g_kv  [4096*1024];
__device__ __align__(16) float g_sc  [16*1024*256];
__device__ int g_starts[4*1025 + 4*257 + 4*65];

__device__ __align__(16) bf g_lnh[4096*512],  g_lnl[4096*512];
__device__ __align__(16) bf g_ln2h[4096*512], g_ln2l[4096*512];
__device__ __align__(16) bf g_hh [4096*1024], g_hl [4096*1024];
__device__ __align__(16) bf g_q2h[4096*512],  g_q2l[4096*512];   // i0 bu Q
__device__ __align__(16) bf g_q3h[1024*512],  g_q3l[1024*512];   // i0 td Q
__device__ __align__(16) bf g_q4h[256*512],   g_q4l[256*512];    // i1 td Q
__device__ __align__(16) bf g_q5h[1024*512],  g_q5l[1024*512];   // i1 bu Q
__device__ __align__(16) bf g_kvh[4096*1024], g_kvl[4096*1024];
__device__ __align__(16) bf g_ph [16*1024*256], g_pl [16*1024*256];
__device__ __align__(16) bf g_aoh[4096*512],  g_aol[4096*512];
__device__ __align__(16) bf g_s1h[4*256*512], g_s1l[4*256*512];
__device__ __align__(16) bf g_s2h[4*64*512],  g_s2l[4*64*512];
__device__ __align__(16) bf g_fuh[4096*512],  g_ful[4096*512];
__device__ __align__(16) bf g_vth[16*128*1024], g_vtl[16*128*1024];
__device__ __align__(16) bf g_w1th[3*1024*512], g_w1tl[3*1024*512];
__device__ __align__(16) bf g_w2th[3*512*1024], g_w2tl[3*512*1024];
__device__ __align__(16) bf g_cath[16*512*512], g_catl[16*512*512];

// private scratch for the concurrent small MHA (i1-td: Sq=64, Skv=256)
__device__ __align__(16) float g_kv2[1024*1024];
__device__ __align__(16) float g_sc2[16*64*256];
__device__ __align__(16) bf g_kv2h[1024*1024], g_kv2l[1024*1024];
__device__ __align__(16) bf g_vt2h[16*128*256], g_vt2l[16*128*256];
__device__ __align__(16) bf g_p2h[16*64*256],  g_p2l[16*64*256];
__device__ __align__(16) bf g_ao2h[256*512],   g_ao2l[256*512];

__device__ __forceinline__ void bf16hl(float x, bf& h, bf& l) {
    h = __float2bfloat16(x);
    l = __float2bfloat16(x - __bfloat162float(h));
}

// ---------------- fused boundary scans (ballot prefix) ------------------------
__global__ void starts_all(const int* __restrict__ b0, const int* __restrict__ b1,
                           const int* __restrict__ b2, int* __restrict__ stall) {
    int lvl = blockIdx.x >> 2, batch = blockIdx.x & 3;
    const int* bsrc; int L, nseg; int* st;
    if (lvl == 0)      { bsrc = b0; L = 8192; nseg = 1024; st = stall + batch * 1025; }
    else if (lvl == 1) { bsrc = b1; L = 1024; nseg = 256;  st = stall + 4*1025 + batch * 257; }
    else               { bsrc = b2; L = 256;  nseg = 64;   st = stall + 4*1025 + 4*257 + batch * 65; }
    int t = threadIdx.x;
    int lane = t & 31, w = t >> 5;
    const int* bi = bsrc + (long)batch * L;
    __shared__ int wcnt[8];
    __shared__ int sbase;
    if (t == 0) sbase = 0;
    for (int i = t; i <= nseg; i += 256) st[i] = L;
    __syncthreads();
    for (int base = 0; base < L; base += 256) {
        int i = base + t;                       // L is a multiple of 256
        int v = bi[i];
        unsigned m = __ballot_sync(0xffffffffu, v != 0);
        int pre = __popc(m & ((1u << lane) - 1u));
        if (lane == 0) wcnt[w] = __popc(m);
        __syncthreads();
        int woff = 0;
        #pragma unroll
        for (int k = 0; k < 8; k++) if (k < w) woff += wcnt[k];
        int pos = sbase + woff + pre;
        if (v && pos < nseg) st[pos] = i;
        __syncthreads();
        if (t == 0) {
            int tot = 0;
            #pragma unroll
            for (int k = 0; k < 8; k++) tot += wcnt[k];
            sbase += tot;
        }
        __syncthreads();
    }
    if (t == 0) st[nseg] = L;
}

// ---------------- fused segment mean pool + LN --------------------------------
__global__ void pool_ln_kernel(const float* __restrict__ x, float* __restrict__ seg,
                               bf* __restrict__ yh, bf* __restrict__ yl,
                               const int* __restrict__ starts, int Lin, int nseg,
                               const float* __restrict__ g, const float* __restrict__ bt) {
    int b = blockIdx.y, s0 = blockIdx.x;
    const int* st = starts + (long)b * (nseg + 1);
    int beg = st[s0], end = st[s0 + 1];
    int t = threadIdx.x;
    float4 v = make_float4(0.f, 0.f, 0.f, 0.f);
    for (int r = beg; r < end; r++) {
        float4 u = ((const float4*)(x + ((long)b * Lin + r) * Dm))[t];
        v.x += u.x; v.y += u.y; v.z += u.z; v.w += u.w;
    }
    int c = end - beg; if (c < 1) c = 1;
    float invc = 1.0f / (float)c;
    v.x *= invc; v.y *= invc; v.z *= invc; v.w *= invc;
    long row = (long)b * nseg + s0;
    ((float4*)(seg + row * Dm))[t] = v;
    float s  = v.x + v.y + v.z + v.w;
    float sq = v.x * v.x + v.y * v.y + v.z * v.z + v.w * v.w;
    __shared__ float sh[8];
    __shared__ float stats[2];
    for (int o = 16; o; o >>= 1) {
        s  += __shfl_xor_sync(0xffffffffu, s, o);
        sq += __shfl_xor_sync(0xffffffffu, sq, o);
    }
    int w = t >> 5;
    if ((t & 31) == 0) { sh[w] = s; sh[4 + w] = sq; }
    __syncthreads();
    if (t == 0) {
        float S = sh[0] + sh[1] + sh[2] + sh[3];
        float Q = sh[4] + sh[5] + sh[6] + sh[7];
        float mu = S * (1.0f / 512.0f);
        float var = Q * (1.0f / 512.0f) - mu * mu;
        stats[0] = mu; stats[1] = rsqrtf(var + 1e-5f);
    }
    __syncthreads();
    float mu = stats[0], inv = stats[1];
    float4 gg = ((const float4*)g)[t];
    float4 bb = ((const float4*)bt)[t];
    float o[4];
    o[0] = (v.x - mu) * inv * gg.x + bb.x;
    o[1] = (v.y - mu) * inv * gg.y + bb.y;
    o[2] = (v.z - mu) * inv * gg.z + bb.z;
    o[3] = (v.w - mu) * inv * gg.w + bb.w;
    bf h[4], l[4];
    #pragma unroll
    for (int i = 0; i < 4; i++) bf16hl(o[i], h[i], l[i]);
    *(uint2*)(yh + row * Dm + t * 4) = *(uint2*)h;
    *(uint2*)(yl + row * Dm + t * 4) = *(uint2*)l;
}

// ---------------- layernorm (bf16 hi/lo out) ----------------------------------
__global__ void ln_kernel(const float* __restrict__ x,
                          bf* __restrict__ yh, bf* __restrict__ yl,
                          const float* __restrict__ g, const float* __restrict__ bt) {
    long row = blockIdx.x;
    int t = threadIdx.x;
    float4 v = ((const float4*)(x + row * Dm))[t];
    float s  = v.x + v.y + v.z + v.w;
    float sq = v.x * v.x + v.y * v.y + v.z * v.z + v.w * v.w;
    __shared__ float sh[8];
    __shared__ float stats[2];
    for (int o = 16; o; o >>= 1) {
        s  += __shfl_xor_sync(0xffffffffu, s, o);
        sq += __shfl_xor_sync(0xffffffffu, sq, o);
    }
    int w = t >> 5;
    if ((t & 31) == 0) { sh[w] = s; sh[4 + w] = sq; }
    __syncthreads();
    if (t == 0) {
        float S = sh[0] + sh[1] + sh[2] + sh[3];
        float Q = sh[4] + sh[5] + sh[6] + sh[7];
        float mu = S * (1.0f / 512.0f);
        float var = Q * (1.0f / 512.0f) - mu * mu;
        stats[0] = mu; stats[1] = rsqrtf(var + 1e-5f);
    }
    __syncthreads();
    float mu = stats[0], inv = stats[1];
    float4 gg = ((const float4*)g)[t];
    float4 bb = ((const float4*)bt)[t];
    float o[4];
    o[0] = (v.x - mu) * inv * gg.x + bb.x;
    o[1] = (v.y - mu) * inv * gg.y + bb.y;
    o[2] = (v.z - mu) * inv * gg.z + bb.z;
    o[3] = (v.w - mu) * inv * gg.w + bb.w;
    bf h[4], l[4];
    #pragma unroll
    for (int i = 0; i < 4; i++) bf16hl(o[i], h[i], l[i]);
    *(uint2*)(yh + row * Dm + t * 4) = *(uint2*)h;
    *(uint2*)(yl + row * Dm + t * 4) = *(uint2*)l;
}

// ---------------- registerized row softmax (L<=1024), bf16 hi/lo emit ----------
__global__ void softmax_kernel(const float* __restrict__ sc, int L,
                               bf* __restrict__ ph, bf* __restrict__ pl) {
    long row = blockIdx.x;
    const float* r = sc + row * (long)L;
    int t = threadIdx.x;
    __shared__ float wr[4];
    __shared__ float bval;
    float v[8];
    int cnt = 0;
    float mx = -3.4e38f;
    for (int i = t; i < L; i += 128) {
        v[cnt] = r[i];
        mx = fmaxf(mx, v[cnt]);
        cnt++;
    }
    for (int o = 16; o; o >>= 1) mx = fmaxf(mx, __shfl_xor_sync(0xffffffffu, mx, o));
    if ((t & 31) == 0) wr[t >> 5] = mx;
    __syncthreads();
    if (t == 0) bval = fmaxf(fmaxf(wr[0], wr[1]), fmaxf(wr[2], wr[3]));
    __syncthreads();
    mx = bval;
    float s = 0.f;
    #pragma unroll 8
    for (int j = 0; j < cnt; j++) { v[j] = expf(v[j] - mx); s += v[j]; }
    for (int o = 16; o; o >>= 1) s += __shfl_xor_sync(0xffffffffu, s, o);
    if ((t & 31) == 0) wr[t >> 5] = s;
    __syncthreads();
    if (t == 0) bval = wr[0] + wr[1] + wr[2] + wr[3];
    __syncthreads();
    float inv = 1.0f / bval;
    cnt = 0;
    for (int i = t; i < L; i += 128) {
        float p = v[cnt++] * inv;
        bf h, l; bf16hl(p, h, l);
        ph[row * (long)L + i] = h; pl[row * (long)L + i] = l;
    }
}

// ---------------- transpose + convert -----------------------------------------
__global__ void tconv(const float* __restrict__ in, bf* __restrict__ oh,
                      bf* __restrict__ ol, int ldin, long szb, long szh, int nH,
                      int ldout, long szout) {
    int z = blockIdx.z, bb = z / nH, hh = z % nH;
    const float* src = in + bb * szb + hh * szh;
    oh += (long)z * szout; ol += (long)z * szout;
    __shared__ float tbuf[32][33];
    int r0 = blockIdx.y * 32, c0 = blockIdx.x * 32;
    for (int i = threadIdx.y; i < 32; i += 8)
        tbuf[i][threadIdx.x] = src[(long)(r0 + i) * ldin + c0 + threadIdx.x];
    __syncthreads();
    for (int i = threadIdx.y; i < 32; i += 8) {
        float x = tbuf[threadIdx.x][i];
        bf h, l; bf16hl(x, h, l);
        long o = (long)(c0 + i) * ldout + r0 + threadIdx.x;
        oh[o] = h; ol[o] = l;
    }
}

// ---------------- mma / ldmatrix helpers --------------------------------------
__device__ __forceinline__ void mma16816(float* c, const unsigned* a, const unsigned* b) {
    asm volatile("mma.sync.aligned.m16n8k16.row.col.f32.bf16.bf16.f32 "
        "{%0,%1,%2,%3}, {%4,%5,%6,%7}, {%8,%9}, {%0,%1,%2,%3};"
        : "+f"(c[0]), "+f"(c[1]), "+f"(c[2]), "+f"(c[3])
        : "r"(a[0]), "r"(a[1]), "r"(a[2]), "r"(a[3]), "r"(b[0]), "r"(b[1]));
}
__device__ __forceinline__ void ldsm4(unsigned& r0, unsigned& r1, unsigned& r2,
                                      unsigned& r3, unsigned a) {
    asm volatile("ldmatrix.sync.aligned.m8n8.x4.shared.b16 {%0,%1,%2,%3}, [%4];"
        : "=r"(r0), "=r"(r1), "=r"(r2), "=r"(r3) : "r"(a));
}

__device__ __forceinline__ void epi_emit(
    float x0, float x1, int m, int n, long ldc, long ldres,
    const float* bias, const float* res, float* Cf, bf* Chi, bf* Clo, int doGelu) {
    if (bias) { x0 += bias[n]; x1 += bias[n + 1]; }
    if (doGelu) {
        x0 = 0.5f * x0 * (1.0f + erff(x0 * 0.70710678118654752f));
        x1 = 0.5f * x1 * (1.0f + erff(x1 * 0.70710678118654752f));
    }
    if (res) {
        float2 rv = *(const float2*)(res + (long)m * ldres + n);
        x0 += rv.x; x1 += rv.y;
    }
    long o = (long)m * ldc + n;
    if (Cf) *(float2*)(Cf + o) = make_float2(x0, x1);
    if (Chi) {
        bf h0, l0, h1, l1;
        bf16hl(x0, h0, l0); bf16hl(x1, h1, l1);
        __nv_bfloat162 hv; hv.x = h0; hv.y = h1;
        __nv_bfloat162 lv; lv.x = l0; lv.y = l1;
        *(__nv_bfloat162*)(Chi + o) = hv;
        *(__nv_bfloat162*)(Clo + o) = lv;
    }
}

// ---------------- 128x128 bf3 GEMM with ldmatrix ------------------------------
__global__ void __launch_bounds__(256) gemm_bf3(
    const bf* __restrict__ Ah, const bf* __restrict__ Al,
    const bf* __restrict__ Bh, const bf* __restrict__ Bl,
    const float* __restrict__ bias, const float* __restrict__ res,
    float* Cf, bf* Chi, bf* Clo,
    int K, int lda, int ldb, int ldc, int ldres,
    long sAb, long sAhh, long sBb, long sBhh, long sCb, long sChh, long sRb,
    int nH, float alpha, int doGelu)
{
    int z = blockIdx.z, bb = z / nH, hh = z - bb * nH;
    Ah += bb * sAb + hh * sAhh; Al += bb * sAb + hh * sAhh;
    Bh += bb * sBb + hh * sBhh; Bl += bb * sBb + hh * sBhh;
    long coff = bb * sCb + hh * sChh;
    if (Cf) Cf += coff;
    if (Chi) { Chi += coff; Clo += coff; }
    if (res) res += bb * sRb;

    __shared__ __align__(16) unsigned char smem[49152];

    int tid = threadIdx.x;
    int lrow = tid >> 1, lch = tid & 1;
    int m0 = blockIdx.y * 128, n0 = blockIdx.x * 128;

    const bf* pAh = Ah + (long)(m0 + lrow) * lda + lch * 8;
    const bf* pAl = Al + (long)(m0 + lrow) * lda + lch * 8;
    const bf* pBh = Bh + (long)(n0 + lrow) * ldb + lch * 8;
    const bf* pBl = Bl + (long)(n0 + lrow) * ldb + lch * 8;

    int soff = lrow * 48 + lch * 16;
    uint4 vAh = *(const uint4*)pAh, vAl = *(const uint4*)pAl;
    uint4 vBh = *(const uint4*)pBh, vBl = *(const uint4*)pBl;
    *(uint4*)(smem + soff)                 = vAh;
    *(uint4*)(smem + 6144 + soff)          = vAl;
    *(uint4*)(smem + 24576 + soff)         = vBh;
    *(uint4*)(smem + 24576 + 6144 + soff)  = vBl;
    __syncthreads();

    int wid = tid >> 5, lane = tid & 31;
    int wm = wid & 3, wn = wid >> 2;
    unsigned sbase = (unsigned)__cvta_generic_to_shared(smem);
    int lrel = ((lane & 7) + ((lane >> 3) & 1) * 8) * 48 + (lane >> 4) * 16;
    unsigned aBase = sbase + (unsigned)(wm * 32 * 48 + lrel);
    unsigned bBase = sbase + 24576u + (unsigned)(wn * 64 * 48 + lrel);

    float acc[2][8][4];
    #pragma unroll
    for (int i = 0; i < 2; i++)
        #pragma unroll
        for (int j = 0; j < 8; j++)
            #pragma unroll
            for (int kq = 0; kq < 4; kq++) acc[i][j][kq] = 0.f;

    int nk = K >> 4;
    for (int t = 0; t < nk; t++) {
        int cur = t & 1;
        if (t + 1 < nk) {
            int ko = (t + 1) << 4;
            vAh = *(const uint4*)(pAh + ko); vAl = *(const uint4*)(pAl + ko);
            vBh = *(const uint4*)(pBh + ko); vBl = *(const uint4*)(pBl + ko);
        }
        unsigned aH = aBase + cur * 12288u, aL = aH + 6144u;
        unsigned bH = bBase + cur * 12288u, bL = bH + 6144u;
        unsigned ah[2][4], al[2][4];
        ldsm4(ah[0][0], ah[0][1], ah[0][2], ah[0][3], aH);
        ldsm4(ah[1][0], ah[1][1], ah[1][2], ah[1][3], aH + 768u);
        ldsm4(al[0][0], al[0][1], al[0][2], al[0][3], aL);
        ldsm4(al[1][0], al[1][1], al[1][2], al[1][3], aL + 768u);
        #pragma unroll
        for (int p = 0; p < 4; p++) {
            unsigned h0, h1, h2, h3, l0, l1, l2, l3;
            ldsm4(h0, h1, h2, h3, bH + p * 768u);
            ldsm4(l0, l1, l2, l3, bL + p * 768u);
            unsigned bEv[2] = {h0, h2}, bOd[2] = {h1, h3};
            unsigned cEv[2] = {l0, l2}, cOd[2] = {l1, l3};
            #pragma unroll
            for (int mf = 0; mf < 2; mf++) {
                mma16816(acc[mf][2*p],     ah[mf], bEv);
                mma16816(acc[mf][2*p],     ah[mf], cEv);
                mma16816(acc[mf][2*p],     al[mf], bEv);
                mma16816(acc[mf][2*p + 1], ah[mf], bOd);
                mma16816(acc[mf][2*p + 1], ah[mf], cOd);
                mma16816(acc[mf][2*p + 1], al[mf], bOd);
            }
        }
        if (t + 1 < nk) {
            unsigned nb = (cur ^ 1) * 12288u;
            *(uint4*)(smem + nb + soff)                = vAh;
            *(uint4*)(smem + nb + 6144 + soff)         = vAl;
            *(uint4*)(smem + 24576 + nb + soff)        = vBh;
            *(uint4*)(smem + 24576 + nb + 6144 + soff) = vBl;
        }
        __syncthreads();
    }

    int g = lane >> 2, c = lane & 3;
    #pragma unroll
    for (int mf = 0; mf < 2; mf++)
        #pragma unroll
        for (int half = 0; half < 2; half++) {
            int m = m0 + wm * 32 + mf * 16 + g + half * 8;
            #pragma unroll
            for (int nf = 0; nf < 8; nf++) {
                int n = n0 + wn * 64 + nf * 8 + 2 * c;
                epi_emit(alpha * acc[mf][nf][half*2], alpha * acc[mf][nf][half*2+1],
                         m, n, ldc, ldres, bias, res, Cf, Chi, Clo, doGelu);
            }
        }
}

// ---------------- 64x64 bf3 GEMM (scalar-LDS) ---------------------------------
#define SKW6 72
__global__ void __launch_bounds__(128) gemm_bf3s(
    const bf* __restrict__ Ah, const bf* __restrict__ Al,
    const bf* __restrict__ Bh, const bf* __restrict__ Bl,
    const float* __restrict__ bias, const float* __restrict__ res,
    float* Cf, bf* Chi, bf* Clo,
    int K, int lda, int ldb, int ldc, int ldres,
    long sAb, long sAhh, long sBb, long sBhh, long sCb, long sChh, long sRb,
    int nH, float alpha, int doGelu)
{
    int z = blockIdx.z, bb = z / nH, hh = z - bb * nH;
    Ah += bb * sAb + hh * sAhh; Al += bb * sAb + hh * sAhh;
    Bh += bb * sBb + hh * sBhh; Bl += bb * sBb + hh * sBhh;
    long coff = bb * sCb + hh * sChh;
    if (Cf) Cf += coff;
    if (Chi) { Chi += coff; Clo += coff; }
    if (res) res += bb * sRb;

    __shared__ unsigned sAh[2][8 * SKW6], sAl[2][8 * SKW6];
    __shared__ unsigned sBh[2][8 * SKW6], sBl[2][8 * SKW6];

    int tid = threadIdx.x;
    int row = tid & 63, kh = tid >> 6;
    int m0 = blockIdx.y * 64, n0 = blockIdx.x * 64;

    const bf* pAh = Ah + (long)(m0 + row) * lda + kh * 8;
    const bf* pAl = Al + (long)(m0 + row) * lda + kh * 8;
    const bf* pBh = Bh + (long)(n0 + row) * ldb + kh * 8;
    const bf* pBl = Bl + (long)(n0 + row) * ldb + kh * 8;

    uint4 vAh = *(const uint4*)pAh, vAl = *(const uint4*)pAl;
    uint4 vBh = *(const uint4*)pBh, vBl = *(const uint4*)pBl;
    int sb = kh * 4 * SKW6 + row;
    sAh[0][sb] = vAh.x; sAh[0][sb + SKW6] = vAh.y; sAh[0][sb + 2*SKW6] = vAh.z; sAh[0][sb + 3*SKW6] = vAh.w;
    sAl[0][sb] = vAl.x; sAl[0][sb + SKW6] = vAl.y; sAl[0][sb + 2*SKW6] = vAl.z; sAl[0][sb + 3*SKW6] = vAl.w;
    sBh[0][sb] = vBh.x; sBh[0][sb + SKW6] = vBh.y; sBh[0][sb + 2*SKW6] = vBh.z; sBh[0][sb + 3*SKW6] = vBh.w;
    sBl[0][sb] = vBl.x; sBl[0][sb + SKW6] = vBl.y; sBl[0][sb + 2*SKW6] = vBl.z; sBl[0][sb + 3*SKW6] = vBl.w;
    __syncthreads();

    int wid = tid >> 5, lane = tid & 31;
    int wm = wid & 1, wn = wid >> 1;
    int g = lane >> 2, c = lane & 3;
    int ar0 = wm * 32 + g, bc0 = wn * 32 + g;

    float acc[2][4][4];
    #pragma unroll
    for (int i = 0; i < 2; i++)
        #pragma unroll
        for (int j = 0; j < 4; j++)
            #pragma unroll
            for (int kq = 0; kq < 4; kq++) acc[i][j][kq] = 0.f;

    int nk = K >> 4;
    for (int t = 0; t < nk; t++) {
        int cur = t & 1;
        if (t + 1 < nk) {
            int ko = (t + 1) << 4;
            vAh = *(const uint4*)(pAh + ko); vAl = *(const uint4*)(pAl + ko);
            vBh = *(const uint4*)(pBh + ko); vBl = *(const uint4*)(pBl + ko);
        }
        unsigned ah[2][4], al[2][4], bh[4][2], bl[4][2];
        const unsigned* SA = sAh[cur]; const unsigned* SA2 = sAl[cur];
        const unsigned* SB = sBh[cur]; const unsigned* SB2 = sBl[cur];
        #pragma unroll
        for (int mf = 0; mf < 2; mf++) {
            int r = ar0 + mf * 16;
            ah[mf][0] = SA[c*SKW6 + r];      ah[mf][1] = SA[c*SKW6 + r + 8];
            ah[mf][2] = SA[(c+4)*SKW6 + r];  ah[mf][3] = SA[(c+4)*SKW6 + r + 8];
            al[mf][0] = SA2[c*SKW6 + r];     al[mf][1] = SA2[c*SKW6 + r + 8];
            al[mf][2] = SA2[(c+4)*SKW6 + r]; al[mf][3] = SA2[(c+4)*SKW6 + r + 8];
        }
        #pragma unroll
        for (int nf = 0; nf < 4; nf++) {
            int cc = bc0 + nf * 8;
            bh[nf][0] = SB[c*SKW6 + cc];  bh[nf][1] = SB[(c+4)*SKW6 + cc];
            bl[nf][0] = SB2[c*SKW6 + cc]; bl[nf][1] = SB2[(c+4)*SKW6 + cc];
        }
        #pragma unroll
        for (int mf = 0; mf < 2; mf++)
            #pragma unroll
            for (int nf = 0; nf < 4; nf++) {
                mma16816(acc[mf][nf], ah[mf], bh[nf]);
                mma16816(acc[mf][nf], ah[mf], bl[nf]);
                mma16816(acc[mf][nf], al[mf], bh[nf]);
            }
        if (t + 1 < nk) {
            int nb2 = cur ^ 1;
            sAh[nb2][sb] = vAh.x; sAh[nb2][sb + SKW6] = vAh.y; sAh[nb2][sb + 2*SKW6] = vAh.z; sAh[nb2][sb + 3*SKW6] = vAh.w;
            sAl[nb2][sb] = vAl.x; sAl[nb2][sb + SKW6] = vAl.y; sAl[nb2][sb + 2*SKW6] = vAl.z; sAl[nb2][sb + 3*SKW6] = vAl.w;
            sBh[nb2][sb] = vBh.x; sBh[nb2][sb + SKW6] = vBh.y; sBh[nb2][sb + 2*SKW6] = vBh.z; sBh[nb2][sb + 3*SKW6] = vBh.w;
            sBl[nb2][sb] = vBl.x; sBl[nb2][sb + SKW6] = vBl.y; sBl[nb2][sb + 2*SKW6] = vBl.z; sBl[nb2][sb + 3*SKW6] = vBl.w;
        }
        __syncthreads();
    }

    #pragma unroll
    for (int mf = 0; mf < 2; mf++)
        #pragma unroll
        for (int half = 0; half < 2; half++) {
            int m = m0 + wm * 32 + mf * 16 + g + half * 8;
            #pragma unroll
            for (int nf = 0; nf < 4; nf++) {
                int n = n0 + wn * 32 + nf * 8 + 2 * c;
                epi_emit(alpha * acc[mf][nf][half*2], alpha * acc[mf][nf][half*2+1],
                         m, n, ldc, ldres, bias, res, Cf, Chi, Clo, doGelu);
            }
        }
}

// ---------------- dispatch (stream-aware) --------------------------------------
static void bf3(const bf* Ah, const bf* Al, const bf* Bh, const bf* Bl,
                const float* bias, const float* res,
                float* Cf, bf* Chi, bf* Clo,
                int M, int N, int K, int lda, int ldb, int ldc, int ldres,
                long sAb, long sAh, long sBb, long sBh, long sCb, long sCh, long sRb,
                int nBat, int nH, float alpha, int doGelu, cudaStream_t st) {
    long nb128 = ((M % 128) || (N % 128)) ? 0 : (long)(M/128) * (N/128) * nBat * nH;
    if (nb128 >= 48) {
        dim3 gr(N / 128, M / 128, nBat * nH);
        gemm_bf3<<<gr, 256, 0, st>>>(Ah, Al, Bh, Bl, bias, res, Cf, Chi, Clo,
                                     K, lda, ldb, ldc, ldres,
                                     sAb, sAh, sBb, sBh, sCb, sCh, sRb, nH, alpha, doGelu);
    } else {
        dim3 gr(N / 64, M / 64, nBat * nH);
        gemm_bf3s<<<gr, 128, 0, st>>>(Ah, Al, Bh, Bl, bias, res, Cf, Chi, Clo,
                                      K, lda, ldb, ldc, ldres,
                                      sAb, sAh, sBb, sBh, sCb, sCh, sRb, nH, alpha, doGelu);
    }
}

// ---------------- stream fork/join (graph-capture-safe) ------------------------
static cudaStream_t g_sB = nullptr, g_sC = nullptr, g_sD = nullptr;
static cudaEvent_t g_ev[48];
static cudaEvent_t g_eq4 = nullptr;
static int g_evi = 0;

static void ensure_streams() {
    if (!g_sB) {
        cudaStreamCreateWithFlags(&g_sB, cudaStreamNonBlocking);
        cudaStreamCreateWithFlags(&g_sC, cudaStreamNonBlocking);
        cudaStreamCreateWithFlags(&g_sD, cudaStreamNonBlocking);
        for (int i = 0; i < 48; i++)
            cudaEventCreateWithFlags(&g_ev[i], cudaEventDisableTiming);
        cudaEventCreateWithFlags(&g_eq4, cudaEventDisableTiming);
    }
}
static void forkTo(cudaStream_t dst) {
    cudaEvent_t e = g_ev[g_evi++ % 48];
    cudaEventRecord(e, 0);
    cudaStreamWaitEvent(dst, e, 0);
}
static void joinFrom(cudaStream_t src) {
    cudaEvent_t e = g_ev[g_evi++ % 48];
    cudaEventRecord(e, src);
    cudaStreamWaitEvent(0, e, 0);
}
static void waitMark(cudaStream_t src) {
    cudaEvent_t e = g_ev[g_evi++ % 48];
    cudaEventRecord(e, src);
    cudaStreamWaitEvent(0, e, 0);
}

// ---------------- host pointers ------------------------------------------------
struct Ptrs {
    float *seg0, *seg1, *seg2, *kvf, *scb;
    float *kv2f, *sc2;
    bf *lnh, *lnl, *ln2h, *ln2l, *hh, *hl;
    bf *q2h, *q2l, *q3h, *q3l, *q4h, *q4l, *q5h, *q5l;
    bf *kvh, *kvl, *ph, *pl, *aoh, *aol;
    bf *kv2h, *kv2l, *vt2h, *vt2l, *p2h, *p2l, *ao2h, *ao2l;
    bf *s1h, *s1l, *s2h, *s2l, *fuh, *ful, *vth, *vtl;
    bf *w1th, *w1tl, *w2th, *w2tl, *cath, *catl;
    int *st;
};

// precompute LN + Q projection on stream C
static void qchain(Ptrs& P, const float* src, int rows,
                   const float* lg, const float* lb,
                   const bf* Wh, const bf* Wl, const float* Bv,
                   bf* qh, bf* ql) {
    forkTo(g_sC);
    ln_kernel<<<rows, 128, 0, g_sC>>>(src, P.ln2h, P.ln2l, lg, lb);
    bf3(P.ln2h, P.ln2l, Wh, Wl, Bv, nullptr, nullptr, qh, ql,
        rows, 512, 512, 512, 512, 512, 0, 0,0,0,0,0,0,0, 1,1, 1.f, 0, g_sC);
}

// MHA with precomputed Q, split K/V: scores start after K only
static void mha_pq(Ptrs& P, const bf* qH, const bf* qL, int Sq,
                   const bf* kvHin, const bf* kvLin, int Skv,
                   const bf* Wth, const bf* Wtl, const float* Bv,
                   const float* resid, float* outF, bf* outH, bf* outL) {
    int Mkv = 4 * Skv;
    int Mq = 4 * Sq;
    const float scl = 0.08838834764831845f;
    forkTo(g_sB);
    // K projection (N=512) -> kvh/kvl
    bf3(kvHin, kvLin, Wth + DD, Wtl + DD, Bv + 512, nullptr, nullptr, P.kvh, P.kvl,
        Mkv, 512, 512, 512, 512, 512, 0, 0,0,0,0,0,0,0, 1,1, 1.f, 0, g_sB);
    waitMark(g_sB);   // stream 0 may start scores once K lands
    // V projection (N=512, fp32) + V transpose, still on B
    bf3(kvHin, kvLin, Wth + 2*DD, Wtl + 2*DD, Bv + 2*512, nullptr, P.kvf, nullptr, nullptr,
        Mkv, 512, 512, 512, 512, 512, 0, 0,0,0,0,0,0,0, 1,1, 1.f, 0, g_sB);
    dim3 tb(32, 8);
    tconv<<<dim3(4, Skv/32, 16), tb, 0, g_sB>>>(P.kvf, P.vth, P.vtl,
                                                 512, (long)Skv * 512, 128, 4,
                                                 Skv, (long)128 * Skv);
    joinFrom(g_sC);   // precomputed Q ready
    // scores = alpha * Q K^T   (K in kvh/kvl, ldb=512)
    bf3(qH, qL, P.kvh, P.kvl, nullptr, nullptr, P.scb, nullptr, nullptr,
        Sq, Skv, 128, 512, 512, Skv, 0,
        (long)Sq*512, 128, (long)Skv*512, 128, (long)4*Sq*Skv, (long)Sq*Skv, 0,
        4, 4, scl, 0, 0);
    softmax_kernel<<<16 * Sq, 128>>>(P.scb, Skv, P.ph, P.pl);
    joinFrom(g_sB);   // V^T ready
    bf3(P.ph, P.pl, P.vth, P.vtl, nullptr, nullptr, nullptr, P.aoh, P.aol,
        Sq, 128, Skv, Skv, Skv, 512, 0,
        (long)4*Sq*Skv, (long)Sq*Skv, (long)4*128*Skv, (long)128*Skv,
        (long)Sq*512, 128, 0,
        4, 4, 1.f, 0, 0);
    bf3(P.aoh, P.aol, Wth + 3*DD, Wtl + 3*DD, Bv + 3*512, resid, outF, outH, outL,
        Mq, 512, 512, 512, 512, 512, 512, 0,0,0,0,0,0,0, 1,1, 1.f, 0, 0);
}

// small MHA fully on stream D with private buffers (Sq=64, Skv=256)
static void mha_onD(Ptrs& P, const bf* qH, const bf* qL, int Sq,
                    const bf* kvHin, const bf* kvLin, int Skv,
                    const bf* Wth, const bf* Wtl, const float* Bv,
                    const float* resid, float* outF) {
    int Mkv = 4 * Skv;
    int Mq = 4 * Sq;
    const float scl = 0.08838834764831845f;
    bf3(kvHin, kvLin, Wth + DD, Wtl + DD, Bv + 512, nullptr, P.kv2f, P.kv2h, P.kv2l,
        Mkv, 1024, 512, 512, 512, 1024, 0, 0,0,0,0,0,0,0, 1,1, 1.f, 0, g_sD);
    dim3 tb(32, 8);
    tconv<<<dim3(4, Skv/32, 16), tb, 0, g_sD>>>(P.kv2f + 512, P.vt2h, P.vt2l,
                                                 1024, (long)Skv * 1024, 128, 4,
                                                 Skv, (long)128 * Skv);
    bf3(qH, qL, P.kv2h, P.kv2l, nullptr, nullptr, P.sc2, nullptr, nullptr,
        Sq, Skv, 128, 512, 1024, Skv, 0,
        (long)Sq*512, 128, (long)Skv*1024, 128, (long)4*Sq*Skv, (long)Sq*Skv, 0,
        4, 4, scl, 0, g_sD);
    softmax_kernel<<<16 * Sq, 128, 0, g_sD>>>(P.sc2, Skv, P.p2h, P.p2l);
    bf3(P.p2h, P.p2l, P.vt2h, P.vt2l, nullptr, nullptr, nullptr, P.ao2h, P.ao2l,
        Sq, 128, Skv, Skv, Skv, 512, 0,
        (long)4*Sq*Skv, (long)Sq*Skv, (long)4*128*Skv, (long)128*Skv,
        (long)Sq*512, 128, 0,
        4, 4, 1.f, 0, g_sD);
    bf3(P.ao2h, P.ao2l, Wth + 3*DD, Wtl + 3*DD, Bv + 3*512, resid, outF, nullptr, nullptr,
        Mq, 512, 512, 512, 512, 512, 512, 0,0,0,0,0,0,0, 1,1, 1.f, 0, g_sD);
}

extern "C" void kernel_launch(void* const* d_in, const int* in_sizes, int n_in,
                              void* d_out, int out_size) {
    const float* h_bytes   = (const float*)d_in[0];
    const int*   b0        = (const int*)d_in[1];
    const int*   b1        = (const int*)d_in[2];
    const int*   b2        = (const int*)d_in[3];
    const float* mlp_ln_g  = (const float*)d_in[4];
    const float* mlp_ln_b  = (const float*)d_in[5];
    const float* mlp_w1    = (const float*)d_in[6];
    const float* mlp_b1    = (const float*)d_in[7];
    const float* mlp_w2    = (const float*)d_in[8];
    const float* mlp_b2    = (const float*)d_in[9];
    const float* ca_w      = (const float*)d_in[10];
    const float* ca_b      = (const float*)d_in[11];
    const float* ca_ln_g   = (const float*)d_in[12];
    const float* ca_ln_b   = (const float*)d_in[13];

    ensure_streams();
    g_evi = 0;

    Ptrs P;
    cudaGetSymbolAddress((void**)&P.seg0, g_seg0);
    cudaGetSymbolAddress((void**)&P.seg1, g_seg1);
    cudaGetSymbolAddress((void**)&P.seg2, g_seg2);
    cudaGetSymbolAddress((void**)&P.kvf, g_kv);
    cudaGetSymbolAddress((void**)&P.scb, g_sc);
    cudaGetSymbolAddress((void**)&P.kv2f, g_kv2);
    cudaGetSymbolAddress((void**)&P.sc2, g_sc2);
    cudaGetSymbolAddress((void**)&P.st, g_starts);
    cudaGetSymbolAddress((void**)&P.lnh, g_lnh);   cudaGetSymbolAddress((void**)&P.lnl, g_lnl);
    cudaGetSymbolAddress((void**)&P.ln2h, g_ln2h); cudaGetSymbolAddress((void**)&P.ln2l, g_ln2l);
    cudaGetSymbolAddress((void**)&P.hh, g_hh);     cudaGetSymbolAddress((void**)&P.hl, g_hl);
    cudaGetSymbolAddress((void**)&P.q2h, g_q2h);   cudaGetSymbolAddress((void**)&P.q2l, g_q2l);
    cudaGetSymbolAddress((void**)&P.q3h, g_q3h);   cudaGetSymbolAddress((void**)&P.q3l, g_q3l);
    cudaGetSymbolAddress((void**)&P.q4h, g_q4h);   cudaGetSymbolAddress((void**)&P.q4l, g_q4l);
    cudaGetSymbolAddress((void**)&P.q5h, g_q5h);   cudaGetSymbolAddress((void**)&P.q5l, g_q5l);
    cudaGetSymbolAddress((void**)&P.kvh, g_kvh);   cudaGetSymbolAddress((void**)&P.kvl, g_kvl);
    cudaGetSymbolAddress((void**)&P.ph, g_ph);     cudaGetSymbolAddress((void**)&P.pl, g_pl);
    cudaGetSymbolAddress((void**)&P.aoh, g_aoh);   cudaGetSymbolAddress((void**)&P.aol, g_aol);
    cudaGetSymbolAddress((void**)&P.kv2h, g_kv2h); cudaGetSymbolAddress((void**)&P.kv2l, g_kv2l);
    cudaGetSymbolAddress((void**)&P.vt2h, g_vt2h); cudaGetSymbolAddress((void**)&P.vt2l, g_vt2l);
    cudaGetSymbolAddress((void**)&P.p2h, g_p2h);   cudaGetSymbolAddress((void**)&P.p2l, g_p2l);
    cudaGetSymbolAddress((void**)&P.ao2h, g_ao2h); cudaGetSymbolAddress((void**)&P.ao2l, g_ao2l);
    cudaGetSymbolAddress((void**)&P.s1h, g_s1h);   cudaGetSymbolAddress((void**)&P.s1l, g_s1l);
    cudaGetSymbolAddress((void**)&P.s2h, g_s2h);   cudaGetSymbolAddress((void**)&P.s2l, g_s2l);
    cudaGetSymbolAddress((void**)&P.fuh, g_fuh);   cudaGetSymbolAddress((void**)&P.ful, g_ful);
    cudaGetSymbolAddress((void**)&P.vth, g_vth);   cudaGetSymbolAddress((void**)&P.vtl, g_vtl);
    cudaGetSymbolAddress((void**)&P.w1th, g_w1th); cudaGetSymbolAddress((void**)&P.w1tl, g_w1tl);
    cudaGetSymbolAddress((void**)&P.w2th, g_w2th); cudaGetSymbolAddress((void**)&P.w2tl, g_w2tl);
    cudaGetSymbolAddress((void**)&P.cath, g_cath); cudaGetSymbolAddress((void**)&P.catl, g_catl);

    int* st0 = P.st;
    int* st1 = P.st + 4 * 1025;
    int* st2 = st1 + 4 * 257;

    float* OUT0 = (float*)d_out;
    float* OUT1 = OUT0 + (long)4 * 1024 * 512;
    float* OUT2 = OUT1 + (long)4 * 256 * 512;

    const bf* WhI1 = P.cath + (long)8 * DD;
    const bf* WlI1 = P.catl + (long)8 * DD;
    const float* BvI1 = ca_b + (long)8 * 512;

    dim3 tb(32, 8);
    forkTo(g_sB);
    tconv<<<dim3(32, 16, 3), tb, 0, g_sB>>>(mlp_w1, P.w1th, P.w1tl, 1024, 512*1024, 0, 1, 512, 524288);
    tconv<<<dim3(16, 32, 3), tb, 0, g_sB>>>(mlp_w2, P.w2th, P.w2tl, 512, 524288, 0, 1, 1024, 524288);
    tconv<<<dim3(16, 16, 16), tb, 0, g_sB>>>(ca_w, P.cath, P.catl, 512, 262144, 0, 1, 512, 262144);

    starts_all<<<12, 256>>>(b0, b1, b2, P.st);

    // ---- level 0 ----
    pool_ln_kernel<<<dim3(1024, 4), 128>>>(h_bytes, P.seg0, P.lnh, P.lnl, st0,
                                           8192, 1024, mlp_ln_g, mlp_ln_b);
    joinFrom(g_sB);
    bf3(P.lnh, P.lnl, P.w1th, P.w1tl, mlp_b1, nullptr, nullptr, P.hh, P.hl,
        4096, 1024, 512, 512, 512, 1024, 0, 0,0,0,0,0,0,0, 1,1, 1.f, 1, 0);
    bf3(P.hh, P.hl, P.w2th, P.w2tl, mlp_b2, P.seg0, P.seg0, nullptr, nullptr,
        4096, 512, 1024, 1024, 1024, 512, 512, 0,0,0,0,0,0,0, 1,1, 1.f, 0, 0);
    qchain(P, P.seg0, 4096, ca_ln_g, ca_ln_b, P.cath, P.catl, ca_b, P.q2h, P.q2l);

    // ---- level 1 ----
    pool_ln_kernel<<<dim3(256, 4), 128>>>(P.seg0, P.seg1, P.lnh, P.lnl, st1,
                                          1024, 256, mlp_ln_g + 512, mlp_ln_b + 512);
    bf3(P.lnh, P.lnl, P.w1th + 524288, P.w1tl + 524288, mlp_b1 + 1024, nullptr,
        nullptr, P.hh, P.hl,
        1024, 1024, 512, 512, 512, 1024, 0, 0,0,0,0,0,0,0, 1,1, 1.f, 1, 0);
    bf3(P.hh, P.hl, P.w2th + 524288, P.w2tl + 524288, mlp_b2 + 512, P.seg1,
        P.seg1, nullptr, nullptr,
        1024, 512, 1024, 1024, 1024, 512, 512, 0,0,0,0,0,0,0, 1,1, 1.f, 0, 0);
    qchain(P, P.seg1, 1024, ca_ln_g + 1024, ca_ln_b + 1024, WhI1, WlI1, BvI1,
           P.q5h, P.q5l);

    // ---- level 2 ----
    pool_ln_kernel<<<dim3(64, 4), 128>>>(P.seg1, P.seg2, P.lnh, P.lnl, st2,
                                         256, 64, mlp_ln_g + 1024, mlp_ln_b + 1024);
    bf3(P.lnh, P.lnl, P.w1th + 2*524288, P.w1tl + 2*524288, mlp_b1 + 2048, nullptr,
        nullptr, P.hh, P.hl,
        256, 1024, 512, 512, 512, 1024, 0, 0,0,0,0,0,0,0, 1,1, 1.f, 1, 0);
    bf3(P.hh, P.hl, P.w2th + 2*524288, P.w2tl + 2*524288, mlp_b2 + 1024, P.seg2,
        P.seg2, P.s2h, P.s2l,
        256, 512, 1024, 1024, 1024, 512, 512, 0,0,0,0,0,0,0, 1,1, 1.f, 0, 0);
    qchain(P, P.seg2, 256, ca_ln_g + 1536, ca_ln_b + 1536, WhI1 + 4*DD, WlI1 + 4*DD,
           BvI1 + 4*512, P.q4h, P.q4l);
    cudaEventRecord(g_eq4, g_sC);

    // ---- i1 bu (critical): fu1 -> seg1 (+s1h/s1l) ----
    mha_pq(P, P.q5h, P.q5l, 256, P.s2h, P.s2l, 64, WhI1, WlI1, BvI1,
           P.seg1, P.seg1, P.s1h, P.s1l);
    // i0-td Q chain (needs seg1 = fu1)
    qchain(P, P.seg1, 1024, ca_ln_g + 512, ca_ln_b + 512, P.cath + 4*DD, P.catl + 4*DD,
           ca_b + 4*512, P.q3h, P.q3l);

    // ---- i1 td on stream D, concurrent with i0 bu ----
    forkTo(g_sD);
    cudaStreamWaitEvent(g_sD, g_eq4, 0);
    mha_onD(P, P.q4h, P.q4l, 64, P.s1h, P.s1l, 256, WhI1 + 4*DD, WlI1 + 4*DD,
            BvI1 + 4*512, P.seg2, OUT2);

    // ---- i0 bu: fu0 -> OUT0 (+fuh/ful) ----
    mha_pq(P, P.q2h, P.q2l, 1024, P.s1h, P.s1l, 256, P.cath, P.catl, ca_b,
           P.seg0, OUT0, P.fuh, P.ful);
    // ---- i0 td: cu0 -> OUT1 ----
    mha_pq(P, P.q3h, P.q3l, 256, P.fuh, P.ful, 1024, P.cath + 4*DD, P.catl + 4*DD,
           ca_b + 4*512, P.seg1, OUT1, nullptr, nullptr);

    joinFrom(g_sD);
}

// round 16
// speedup vs baseline: 1.0938x; 1.0938x over previous
#include <cuda_runtime.h>
#include <cuda_fp16.h>
#include <math.h>
#include <stdint.h>

#define Dm 512
#define DD (512*512)
typedef __half hf;

// ---------------- scratch (device globals; no allocation) ----------------
__device__ __align__(16) float g_seg0[4*1024*512];
__device__ __align__(16) float g_seg1[4*256*512];
__device__ __align__(16) float g_seg2[4*64*512];
__device__ __align__(16) float g_kv  [4096*1024];
__device__ __align__(16) float g_sc  [16*1024*256];
__device__ int g_starts[4*1025 + 4*257 + 4*65];

// activations: single fp16
__device__ __align__(16) hf g_lnh[4096*512];
__device__ __align__(16) hf g_ln2h[4096*512];
__device__ __align__(16) hf g_hh [4096*1024];
__device__ __align__(16) hf g_q2h[4096*512];
__device__ __align__(16) hf g_q3h[1024*512];
__device__ __align__(16) hf g_q4h[256*512];
__device__ __align__(16) hf g_q5h[1024*512];
__device__ __align__(16) hf g_ph [16*1024*256];
__device__ __align__(16) hf g_aoh[4096*512];
__device__ __align__(16) hf g_s1h[4*256*512];
__device__ __align__(16) hf g_s2h[4*64*512];
__device__ __align__(16) hf g_fuh[4096*512];
// B-side operands: fp16 hi/lo pairs
__device__ __align__(16) hf g_kvh[4096*512], g_kvl[4096*512];
__device__ __align__(16) hf g_vth[16*128*1024], g_vtl[16*128*1024];
__device__ __align__(16) hf g_w1th[3*1024*512], g_w1tl[3*1024*512];
__device__ __align__(16) hf g_w2th[3*512*1024], g_w2tl[3*512*1024];
__device__ __align__(16) hf g_cath[16*512*512], g_catl[16*512*512];

// private scratch for the concurrent small MHA (i1-td: Sq=64, Skv=256)
__device__ __align__(16) float g_kv2[1024*512];
__device__ __align__(16) float g_sc2[16*64*256];
__device__ __align__(16) hf g_kv2h[1024*512], g_kv2l[1024*512];
__device__ __align__(16) hf g_vt2h[16*128*256], g_vt2l[16*128*256];
__device__ __align__(16) hf g_p2h[16*64*256];
__device__ __align__(16) hf g_ao2h[256*512];

__device__ __forceinline__ void f16hl(float x, hf& h, hf& l) {
    h = __float2half_rn(x);
    l = __float2half_rn(x - __half2float(h));
}

// ---------------- fused boundary scans (ballot prefix) ------------------------
__global__ void starts_all(const int* __restrict__ b0, const int* __restrict__ b1,
                           const int* __restrict__ b2, int* __restrict__ stall) {
    int lvl = blockIdx.x >> 2, batch = blockIdx.x & 3;
    const int* bsrc; int L, nseg; int* st;
    if (lvl == 0)      { bsrc = b0; L = 8192; nseg = 1024; st = stall + batch * 1025; }
    else if (lvl == 1) { bsrc = b1; L = 1024; nseg = 256;  st = stall + 4*1025 + batch * 257; }
    else               { bsrc = b2; L = 256;  nseg = 64;   st = stall + 4*1025 + 4*257 + batch * 65; }
    int t = threadIdx.x;
    int lane = t & 31, w = t >> 5;
    const int* bi = bsrc + (long)batch * L;
    __shared__ int wcnt[8];
    __shared__ int sbase;
    if (t == 0) sbase = 0;
    for (int i = t; i <= nseg; i += 256) st[i] = L;
    __syncthreads();
    for (int base = 0; base < L; base += 256) {
        int i = base + t;
        int v = bi[i];
        unsigned m = __ballot_sync(0xffffffffu, v != 0);
        int pre = __popc(m & ((1u << lane) - 1u));
        if (lane == 0) wcnt[w] = __popc(m);
        __syncthreads();
        int woff = 0;
        #pragma unroll
        for (int k = 0; k < 8; k++) if (k < w) woff += wcnt[k];
        int pos = sbase + woff + pre;
        if (v && pos < nseg) st[pos] = i;
        __syncthreads();
        if (t == 0) {
            int tot = 0;
            #pragma unroll
            for (int k = 0; k < 8; k++) tot += wcnt[k];
            sbase += tot;
        }
        __syncthreads();
    }
    if (t == 0) st[nseg] = L;
}

// ---------------- fused segment mean pool + LN (fp16 emit) --------------------
__global__ void pool_ln_kernel(const float* __restrict__ x, float* __restrict__ seg,
                               hf* __restrict__ yh,
                               const int* __restrict__ starts, int Lin, int nseg,
                               const float* __restrict__ g, const float* __restrict__ bt) {
    int b = blockIdx.y, s0 = blockIdx.x;
    const int* st = starts + (long)b * (nseg + 1);
    int beg = st[s0], end = st[s0 + 1];
    int t = threadIdx.x;
    float4 v = make_float4(0.f, 0.f, 0.f, 0.f);
    for (int r = beg; r < end; r++) {
        float4 u = ((const float4*)(x + ((long)b * Lin + r) * Dm))[t];
        v.x += u.x; v.y += u.y; v.z += u.z; v.w += u.w;
    }
    int c = end - beg; if (c < 1) c = 1;
    float invc = 1.0f / (float)c;
    v.x *= invc; v.y *= invc; v.z *= invc; v.w *= invc;
    long row = (long)b * nseg + s0;
    ((float4*)(seg + row * Dm))[t] = v;
    float s  = v.x + v.y + v.z + v.w;
    float sq = v.x * v.x + v.y * v.y + v.z * v.z + v.w * v.w;
    __shared__ float sh[8];
    __shared__ float stats[2];
    for (int o = 16; o; o >>= 1) {
        s  += __shfl_xor_sync(0xffffffffu, s, o);
        sq += __shfl_xor_sync(0xffffffffu, sq, o);
    }
    int w = t >> 5;
    if ((t & 31) == 0) { sh[w] = s; sh[4 + w] = sq; }
    __syncthreads();
    if (t == 0) {
        float S = sh[0] + sh[1] + sh[2] + sh[3];
        float Q = sh[4] + sh[5] + sh[6] + sh[7];
        float mu = S * (1.0f / 512.0f);
        float var = Q * (1.0f / 512.0f) - mu * mu;
        stats[0] = mu; stats[1] = rsqrtf(var + 1e-5f);
    }
    __syncthreads();
    float mu = stats[0], inv = stats[1];
    float4 gg = ((const float4*)g)[t];
    float4 bb = ((const float4*)bt)[t];
    hf h[4];
    h[0] = __float2half_rn((v.x - mu) * inv * gg.x + bb.x);
    h[1] = __float2half_rn((v.y - mu) * inv * gg.y + bb.y);
    h[2] = __float2half_rn((v.z - mu) * inv * gg.z + bb.z);
    h[3] = __float2half_rn((v.w - mu) * inv * gg.w + bb.w);
    *(uint2*)(yh + row * Dm + t * 4) = *(uint2*)h;
}

// ---------------- layernorm (fp16 emit) ----------------------------------------
__global__ void ln_kernel(const float* __restrict__ x, hf* __restrict__ yh,
                          const float* __restrict__ g, const float* __restrict__ bt) {
    long row = blockIdx.x;
    int t = threadIdx.x;
    float4 v = ((const float4*)(x + row * Dm))[t];
    float s  = v.x + v.y + v.z + v.w;
    float sq = v.x * v.x + v.y * v.y + v.z * v.z + v.w * v.w;
    __shared__ float sh[8];
    __shared__ float stats[2];
    for (int o = 16; o; o >>= 1) {
        s  += __shfl_xor_sync(0xffffffffu, s, o);
        sq += __shfl_xor_sync(0xffffffffu, sq, o);
    }
    int w = t >> 5;
    if ((t & 31) == 0) { sh[w] = s; sh[4 + w] = sq; }
    __syncthreads();
    if (t == 0) {
        float S = sh[0] + sh[1] + sh[2] + sh[3];
        float Q = sh[4] + sh[5] + sh[6] + sh[7];
        float mu = S * (1.0f / 512.0f);
        float var = Q * (1.0f / 512.0f) - mu * mu;
        stats[0] = mu; stats[1] = rsqrtf(var + 1e-5f);
    }
    __syncthreads();
    float mu = stats[0], inv = stats[1];
    float4 gg = ((const float4*)g)[t];
    float4 bb = ((const float4*)bt)[t];
    hf h[4];
    h[0] = __float2half_rn((v.x - mu) * inv * gg.x + bb.x);
    h[1] = __float2half_rn((v.y - mu) * inv * gg.y + bb.y);
    h[2] = __float2half_rn((v.z - mu) * inv * gg.z + bb.z);
    h[3] = __float2half_rn((v.w - mu) * inv * gg.w + bb.w);
    *(uint2*)(yh + row * Dm + t * 4) = *(uint2*)h;
}

// ---------------- registerized row softmax (fp16 emit) -------------------------
__global__ void softmax_kernel(const float* __restrict__ sc, int L,
                               hf* __restrict__ ph) {
    long row = blockIdx.x;
    const float* r = sc + row * (long)L;
    int t = threadIdx.x;
    __shared__ float wr[4];
    __shared__ float bval;
    float v[8];
    int cnt = 0;
    float mx = -3.4e38f;
    for (int i = t; i < L; i += 128) {
        v[cnt] = r[i];
        mx = fmaxf(mx, v[cnt]);
        cnt++;
    }
    for (int o = 16; o; o >>= 1) mx = fmaxf(mx, __shfl_xor_sync(0xffffffffu, mx, o));
    if ((t & 31) == 0) wr[t >> 5] = mx;
    __syncthreads();
    if (t == 0) bval = fmaxf(fmaxf(wr[0], wr[1]), fmaxf(wr[2], wr[3]));
    __syncthreads();
    mx = bval;
    float s = 0.f;
    #pragma unroll 8
    for (int j = 0; j < cnt; j++) { v[j] = expf(v[j] - mx); s += v[j]; }
    for (int o = 16; o; o >>= 1) s += __shfl_xor_sync(0xffffffffu, s, o);
    if ((t & 31) == 0) wr[t >> 5] = s;
    __syncthreads();
    if (t == 0) bval = wr[0] + wr[1] + wr[2] + wr[3];
    __syncthreads();
    float inv = 1.0f / bval;
    cnt = 0;
    for (int i = t; i < L; i += 128)
        ph[row * (long)L + i] = __float2half_rn(v[cnt++] * inv);
}

// ---------------- transpose + convert (fp16 hi/lo pair) -----------------------
__global__ void tconv(const float* __restrict__ in, hf* __restrict__ oh,
                      hf* __restrict__ ol, int ldin, long szb, long szh, int nH,
                      int ldout, long szout) {
    int z = blockIdx.z, bb = z / nH, hh = z % nH;
    const float* src = in + bb * szb + hh * szh;
    oh += (long)z * szout; ol += (long)z * szout;
    __shared__ float tbuf[32][33];
    int r0 = blockIdx.y * 32, c0 = blockIdx.x * 32;
    for (int i = threadIdx.y; i < 32; i += 8)
        tbuf[i][threadIdx.x] = src[(long)(r0 + i) * ldin + c0 + threadIdx.x];
    __syncthreads();
    for (int i = threadIdx.y; i < 32; i += 8) {
        float x = tbuf[threadIdx.x][i];
        hf h, l; f16hl(x, h, l);
        long o = (long)(c0 + i) * ldout + r0 + threadIdx.x;
        oh[o] = h; ol[o] = l;
    }
}

// ---------------- mma / ldmatrix helpers --------------------------------------
__device__ __forceinline__ void mma16816(float* c, const unsigned* a, const unsigned* b) {
    asm volatile("mma.sync.aligned.m16n8k16.row.col.f32.f16.f16.f32 "
        "{%0,%1,%2,%3}, {%4,%5,%6,%7}, {%8,%9}, {%0,%1,%2,%3};"
        : "+f"(c[0]), "+f"(c[1]), "+f"(c[2]), "+f"(c[3])
        : "r"(a[0]), "r"(a[1]), "r"(a[2]), "r"(a[3]), "r"(b[0]), "r"(b[1]));
}
__device__ __forceinline__ void ldsm4(unsigned& r0, unsigned& r1, unsigned& r2,
                                      unsigned& r3, unsigned a) {
    asm volatile("ldmatrix.sync.aligned.m8n8.x4.shared.b16 {%0,%1,%2,%3}, [%4];"
        : "=r"(r0), "=r"(r1), "=r"(r2), "=r"(r3) : "r"(a));
}

__device__ __forceinline__ void epi_emit(
    float x0, float x1, int m, int n, long ldc, long ldres,
    const float* bias, const float* res, float* Cf, hf* Chi, hf* Clo, int doGelu) {
    if (bias) { x0 += bias[n]; x1 += bias[n + 1]; }
    if (doGelu) {
        x0 = 0.5f * x0 * (1.0f + erff(x0 * 0.70710678118654752f));
        x1 = 0.5f * x1 * (1.0f + erff(x1 * 0.70710678118654752f));
    }
    if (res) {
        float2 rv = *(const float2*)(res + (long)m * ldres + n);
        x0 += rv.x; x1 += rv.y;
    }
    long o = (long)m * ldc + n;
    if (Cf) *(float2*)(Cf + o) = make_float2(x0, x1);
    if (Chi) {
        if (Clo) {
            hf h0, l0, h1, l1;
            f16hl(x0, h0, l0); f16hl(x1, h1, l1);
            __half2 hv; hv.x = h0; hv.y = h1;
            __half2 lv; lv.x = l0; lv.y = l1;
            *(__half2*)(Chi + o) = hv;
            *(__half2*)(Clo + o) = lv;
        } else {
            __half2 hv; hv.x = __float2half_rn(x0); hv.y = __float2half_rn(x1);
            *(__half2*)(Chi + o) = hv;
        }
    }
}

// ---------------- 128x128 fp16 split-2 GEMM (A single, B hi/lo) ---------------
// smem: A stage s @ s*6144; B stage s @ 12288 + s*12288 (Bh), +6144 (Bl)
__global__ void __launch_bounds__(256) gemm_s2(
    const hf* __restrict__ A,
    const hf* __restrict__ Bh, const hf* __restrict__ Bl,
    const float* __restrict__ bias, const float* __restrict__ res,
    float* Cf, hf* Chi, hf* Clo,
    int K, int lda, int ldb, int ldc, int ldres,
    long sAb, long sAhh, long sBb, long sBhh, long sCb, long sChh, long sRb,
    int nH, float alpha, int doGelu)
{
    int z = blockIdx.z, bb = z / nH, hh = z - bb * nH;
    A += bb * sAb + hh * sAhh;
    Bh += bb * sBb + hh * sBhh; Bl += bb * sBb + hh * sBhh;
    long coff = bb * sCb + hh * sChh;
    if (Cf) Cf += coff;
    if (Chi) { Chi += coff; if (Clo) Clo += coff; }
    if (res) res += bb * sRb;

    __shared__ __align__(16) unsigned char smem[36864];

    int tid = threadIdx.x;
    int lrow = tid >> 1, lch = tid & 1;
    int m0 = blockIdx.y * 128, n0 = blockIdx.x * 128;

    const hf* pA  = A  + (long)(m0 + lrow) * lda + lch * 8;
    const hf* pBh = Bh + (long)(n0 + lrow) * ldb + lch * 8;
    const hf* pBl = Bl + (long)(n0 + lrow) * ldb + lch * 8;

    int soff = lrow * 48 + lch * 16;
    uint4 vA = *(const uint4*)pA;
    uint4 vBh = *(const uint4*)pBh, vBl = *(const uint4*)pBl;
    *(uint4*)(smem + soff)                 = vA;
    *(uint4*)(smem + 12288 + soff)         = vBh;
    *(uint4*)(smem + 12288 + 6144 + soff)  = vBl;
    __syncthreads();

    int wid = tid >> 5, lane = tid & 31;
    int wm = wid & 3, wn = wid >> 2;
    unsigned sbase = (unsigned)__cvta_generic_to_shared(smem);
    int lrel = ((lane & 7) + ((lane >> 3) & 1) * 8) * 48 + (lane >> 4) * 16;
    unsigned aBase = sbase + (unsigned)(wm * 32 * 48 + lrel);
    unsigned bBase = sbase + 12288u + (unsigned)(wn * 64 * 48 + lrel);

    float acc[2][8][4];
    #pragma unroll
    for (int i = 0; i < 2; i++)
        #pragma unroll
        for (int j = 0; j < 8; j++)
            #pragma unroll
            for (int kq = 0; kq < 4; kq++) acc[i][j][kq] = 0.f;

    int nk = K >> 4;
    for (int t = 0; t < nk; t++) {
        int cur = t & 1;
        if (t + 1 < nk) {
            int ko = (t + 1) << 4;
            vA = *(const uint4*)(pA + ko);
            vBh = *(const uint4*)(pBh + ko); vBl = *(const uint4*)(pBl + ko);
        }
        unsigned aAddr = aBase + cur * 6144u;
        unsigned bH = bBase + cur * 12288u, bL = bH + 6144u;
        unsigned a[2][4];
        ldsm4(a[0][0], a[0][1], a[0][2], a[0][3], aAddr);
        ldsm4(a[1][0], a[1][1], a[1][2], a[1][3], aAddr + 768u);
        #pragma unroll
        for (int p = 0; p < 4; p++) {
            unsigned h0, h1, h2, h3, l0, l1, l2, l3;
            ldsm4(h0, h1, h2, h3, bH + p * 768u);
            ldsm4(l0, l1, l2, l3, bL + p * 768u);
            unsigned bEv[2] = {h0, h2}, bOd[2] = {h1, h3};
            unsigned cEv[2] = {l0, l2}, cOd[2] = {l1, l3};
            #pragma unroll
            for (int mf = 0; mf < 2; mf++) {
                mma16816(acc[mf][2*p],     a[mf], bEv);
                mma16816(acc[mf][2*p],     a[mf], cEv);
                mma16816(acc[mf][2*p + 1], a[mf], bOd);
                mma16816(acc[mf][2*p + 1], a[mf], cOd);
            }
        }
        if (t + 1 < nk) {
            unsigned nb = (cur ^ 1);
            *(uint4*)(smem + nb * 6144 + soff)                  = vA;
            *(uint4*)(smem + 12288 + nb * 12288 + soff)         = vBh;
            *(uint4*)(smem + 12288 + nb * 12288 + 6144 + soff)  = vBl;
        }
        __syncthreads();
    }

    int g = lane >> 2, c = lane & 3;
    #pragma unroll
    for (int mf = 0; mf < 2; mf++)
        #pragma unroll
        for (int half = 0; half < 2; half++) {
            int m = m0 + wm * 32 + mf * 16 + g + half * 8;
            #pragma unroll
            for (int nf = 0; nf < 8; nf++) {
                int n = n0 + wn * 64 + nf * 8 + 2 * c;
                epi_emit(alpha * acc[mf][nf][half*2], alpha * acc[mf][nf][half*2+1],
                         m, n, ldc, ldres, bias, res, Cf, Chi, Clo, doGelu);
            }
        }
}

// ---------------- 64x64 fp16 split-2 GEMM (scalar-LDS) ------------------------
#define SKW6 72
__global__ void __launch_bounds__(128) gemm_s2s(
    const hf* __restrict__ A,
    const hf* __restrict__ Bh, const hf* __restrict__ Bl,
    const float* __restrict__ bias, const float* __restrict__ res,
    float* Cf, hf* Chi, hf* Clo,
    int K, int lda, int ldb, int ldc, int ldres,
    long sAb, long sAhh, long sBb, long sBhh, long sCb, long sChh, long sRb,
    int nH, float alpha, int doGelu)
{
    int z = blockIdx.z, bb = z / nH, hh = z - bb * nH;
    A += bb * sAb + hh * sAhh;
    Bh += bb * sBb + hh * sBhh; Bl += bb * sBb + hh * sBhh;
    long coff = bb * sCb + hh * sChh;
    if (Cf) Cf += coff;
    if (Chi) { Chi += coff; if (Clo) Clo += coff; }
    if (res) res += bb * sRb;

    __shared__ unsigned sA[2][8 * SKW6];
    __shared__ unsigned sBh[2][8 * SKW6], sBl[2][8 * SKW6];

    int tid = threadIdx.x;
    int row = tid & 63, kh = tid >> 6;
    int m0 = blockIdx.y * 64, n0 = blockIdx.x * 64;

    const hf* pA  = A  + (long)(m0 + row) * lda + kh * 8;
    const hf* pBh = Bh + (long)(n0 + row) * ldb + kh * 8;
    const hf* pBl = Bl + (long)(n0 + row) * ldb + kh * 8;

    uint4 vA = *(const uint4*)pA;
    uint4 vBh = *(const uint4*)pBh, vBl = *(const uint4*)pBl;
    int sb = kh * 4 * SKW6 + row;
    sA[0][sb] = vA.x; sA[0][sb + SKW6] = vA.y; sA[0][sb + 2*SKW6] = vA.z; sA[0][sb + 3*SKW6] = vA.w;
    sBh[0][sb] = vBh.x; sBh[0][sb + SKW6] = vBh.y; sBh[0][sb + 2*SKW6] = vBh.z; sBh[0][sb + 3*SKW6] = vBh.w;
    sBl[0][sb] = vBl.x; sBl[0][sb + SKW6] = vBl.y; sBl[0][sb + 2*SKW6] = vBl.z; sBl[0][sb + 3*SKW6] = vBl.w;
    __syncthreads();

    int wid = tid >> 5, lane = tid & 31;
    int wm = wid & 1, wn = wid >> 1;
    int g = lane >> 2, c = lane & 3;
    int ar0 = wm * 32 + g, bc0 = wn * 32 + g;

    float acc[2][4][4];
    #pragma unroll
    for (int i = 0; i < 2; i++)
        #pragma unroll
        for (int j = 0; j < 4; j++)
            #pragma unroll
            for (int kq = 0; kq < 4; kq++) acc[i][j][kq] = 0.f;

    int nk = K >> 4;
    for (int t = 0; t < nk; t++) {
        int cur = t & 1;
        if (t + 1 < nk) {
            int ko = (t + 1) << 4;
            vA = *(const uint4*)(pA + ko);
            vBh = *(const uint4*)(pBh + ko); vBl = *(const uint4*)(pBl + ko);
        }
        unsigned a[2][4], bh[4][2], bl[4][2];
        const unsigned* SA = sA[cur];
        const unsigned* SB = sBh[cur]; const unsigned* SB2 = sBl[cur];
        #pragma unroll
        for (int mf = 0; mf < 2; mf++) {
            int r = ar0 + mf * 16;
            a[mf][0] = SA[c*SKW6 + r];      a[mf][1] = SA[c*SKW6 + r + 8];
            a[mf][2] = SA[(c+4)*SKW6 + r];  a[mf][3] = SA[(c+4)*SKW6 + r + 8];
        }
        #pragma unroll
        for (int nf = 0; nf < 4; nf++) {
            int cc = bc0 + nf * 8;
            bh[nf][0] = SB[c*SKW6 + cc];  bh[nf][1] = SB[(c+4)*SKW6 + cc];
            bl[nf][0] = SB2[c*SKW6 + cc]; bl[nf][1] = SB2[(c+4)*SKW6 + cc];
        }
        #pragma unroll
        for (int mf = 0; mf < 2; mf++)
            #pragma unroll
            for (int nf = 0; nf < 4; nf++) {
                mma16816(acc[mf][nf], a[mf], bh[nf]);
                mma16816(acc[mf][nf], a[mf], bl[nf]);
            }
        if (t + 1 < nk) {
            int nb = cur ^ 1;
            sA[nb][sb] = vA.x; sA[nb][sb + SKW6] = vA.y; sA[nb][sb + 2*SKW6] = vA.z; sA[nb][sb + 3*SKW6] = vA.w;
            sBh[nb][sb] = vBh.x; sBh[nb][sb + SKW6] = vBh.y; sBh[nb][sb + 2*SKW6] = vBh.z; sBh[nb][sb + 3*SKW6] = vBh.w;
            sBl[nb][sb] = vBl.x; sBl[nb][sb + SKW6] = vBl.y; sBl[nb][sb + 2*SKW6] = vBl.z; sBl[nb][sb + 3*SKW6] = vBl.w;
        }
        __syncthreads();
    }

    #pragma unroll
    for (int mf = 0; mf < 2; mf++)
        #pragma unroll
        for (int half = 0; half < 2; half++) {
            int m = m0 + wm * 32 + mf * 16 + g + half * 8;
            #pragma unroll
            for (int nf = 0; nf < 4; nf++) {
                int n = n0 + wn * 32 + nf * 8 + 2 * c;
                epi_emit(alpha * acc[mf][nf][half*2], alpha * acc[mf][nf][half*2+1],
                         m, n, ldc, ldres, bias, res, Cf, Chi, Clo, doGelu);
            }
        }
}

// ---------------- dispatch (stream-aware) --------------------------------------
static void s2(const hf* A, const hf* Bh, const hf* Bl,
               const float* bias, const float* res,
               float* Cf, hf* Chi, hf* Clo,
               int M, int N, int K, int lda, int ldb, int ldc, int ldres,
               long sAb, long sAh, long sBb, long sBh, long sCb, long sCh, long sRb,
               int nBat, int nH, float alpha, int doGelu, cudaStream_t st) {
    long nb128 = ((M % 128) || (N % 128)) ? 0 : (long)(M/128) * (N/128) * nBat * nH;
    if (nb128 >= 48) {
        dim3 gr(N / 128, M / 128, nBat * nH);
        gemm_s2<<<gr, 256, 0, st>>>(A, Bh, Bl, bias, res, Cf, Chi, Clo,
                                    K, lda, ldb, ldc, ldres,
                                    sAb, sAh, sBb, sBh, sCb, sCh, sRb, nH, alpha, doGelu);
    } else {
        dim3 gr(N / 64, M / 64, nBat * nH);
        gemm_s2s<<<gr, 128, 0, st>>>(A, Bh, Bl, bias, res, Cf, Chi, Clo,
                                     K, lda, ldb, ldc, ldres,
                                     sAb, sAh, sBb, sBh, sCb, sCh, sRb, nH, alpha, doGelu);
    }
}

// ---------------- stream fork/join (graph-capture-safe) ------------------------
static cudaStream_t g_sB = nullptr, g_sC = nullptr, g_sD = nullptr;
static cudaEvent_t g_ev[48];
static cudaEvent_t g_eq4 = nullptr;
static int g_evi = 0;

static void ensure_streams() {
    if (!g_sB) {
        cudaStreamCreateWithFlags(&g_sB, cudaStreamNonBlocking);
        cudaStreamCreateWithFlags(&g_sC, cudaStreamNonBlocking);
        cudaStreamCreateWithFlags(&g_sD, cudaStreamNonBlocking);
        for (int i = 0; i < 48; i++)
            cudaEventCreateWithFlags(&g_ev[i], cudaEventDisableTiming);
        cudaEventCreateWithFlags(&g_eq4, cudaEventDisableTiming);
    }
}
static void forkTo(cudaStream_t dst) {
    cudaEvent_t e = g_ev[g_evi++ % 48];
    cudaEventRecord(e, 0);
    cudaStreamWaitEvent(dst, e, 0);
}
static void joinFrom(cudaStream_t src) {
    cudaEvent_t e = g_ev[g_evi++ % 48];
    cudaEventRecord(e, src);
    cudaStreamWaitEvent(0, e, 0);
}
static void waitMark(cudaStream_t src) {
    cudaEvent_t e = g_ev[g_evi++ % 48];
    cudaEventRecord(e, src);
    cudaStreamWaitEvent(0, e, 0);
}

// ---------------- host pointers ------------------------------------------------
struct Ptrs {
    float *seg0, *seg1, *seg2, *kvf, *scb;
    float *kv2f, *sc2;
    hf *lnh, *ln2h, *hh;
    hf *q2h, *q3h, *q4h, *q5h;
    hf *kvh, *kvl, *ph, *aoh;
    hf *kv2h, *kv2l, *vt2h, *vt2l, *p2h, *ao2h;
    hf *s1h, *s2h, *fuh, *vth, *vtl;
    hf *w1th, *w1tl, *w2th, *w2tl, *cath, *catl;
    int *st;
};

// precompute LN + Q projection on stream C
static void qchain(Ptrs& P, const float* src, int rows,
                   const float* lg, const float* lb,
                   const hf* Wh, const hf* Wl, const float* Bv, hf* qh) {
    forkTo(g_sC);
    ln_kernel<<<rows, 128, 0, g_sC>>>(src, P.ln2h, lg, lb);
    s2(P.ln2h, Wh, Wl, Bv, nullptr, nullptr, qh, nullptr,
       rows, 512, 512, 512, 512, 512, 0, 0,0,0,0,0,0,0, 1,1, 1.f, 0, g_sC);
}

// MHA with precomputed Q, split K/V: scores start after K only
static void mha_pq(Ptrs& P, const hf* qH, int Sq,
                   const hf* kvHin, int Skv,
                   const hf* Wth, const hf* Wtl, const float* Bv,
                   const float* resid, float* outF, hf* outH) {
    int Mkv = 4 * Skv;
    int Mq = 4 * Sq;
    const float scl = 0.08838834764831845f;
    forkTo(g_sB);
    // K projection (N=512) -> kvh/kvl pair
    s2(kvHin, Wth + DD, Wtl + DD, Bv + 512, nullptr, nullptr, P.kvh, P.kvl,
       Mkv, 512, 512, 512, 512, 512, 0, 0,0,0,0,0,0,0, 1,1, 1.f, 0, g_sB);
    waitMark(g_sB);   // stream 0 may start scores once K lands
    // V projection (fp32) + V transpose (pair), still on B
    s2(kvHin, Wth + 2*DD, Wtl + 2*DD, Bv + 2*512, nullptr, P.kvf, nullptr, nullptr,
       Mkv, 512, 512, 512, 512, 512, 0, 0,0,0,0,0,0,0, 1,1, 1.f, 0, g_sB);
    dim3 tb(32, 8);
    tconv<<<dim3(4, Skv/32, 16), tb, 0, g_sB>>>(P.kvf, P.vth, P.vtl,
                                                 512, (long)Skv * 512, 128, 4,
                                                 Skv, (long)128 * Skv);
    joinFrom(g_sC);   // precomputed Q ready
    // scores = alpha * Q K^T
    s2(qH, P.kvh, P.kvl, nullptr, nullptr, P.scb, nullptr, nullptr,
       Sq, Skv, 128, 512, 512, Skv, 0,
       (long)Sq*512, 128, (long)Skv*512, 128, (long)4*Sq*Skv, (long)Sq*Skv, 0,
       4, 4, scl, 0, 0);
    softmax_kernel<<<16 * Sq, 128>>>(P.scb, Skv, P.ph);
    joinFrom(g_sB);   // V^T ready
    s2(P.ph, P.vth, P.vtl, nullptr, nullptr, nullptr, P.aoh, nullptr,
       Sq, 128, Skv, Skv, Skv, 512, 0,
       (long)4*Sq*Skv, (long)Sq*Skv, (long)4*128*Skv, (long)128*Skv,
       (long)Sq*512, 128, 0,
       4, 4, 1.f, 0, 0);
    s2(P.aoh, Wth + 3*DD, Wtl + 3*DD, Bv + 3*512, resid, outF, outH, nullptr,
       Mq, 512, 512, 512, 512, 512, 512, 0,0,0,0,0,0,0, 1,1, 1.f, 0, 0);
}

// small MHA fully on stream D with private buffers (Sq=64, Skv=256)
static void mha_onD(Ptrs& P, const hf* qH, int Sq,
                    const hf* kvHin, int Skv,
                    const hf* Wth, const hf* Wtl, const float* Bv,
                    const float* resid, float* outF) {
    int Mkv = 4 * Skv;
    int Mq = 4 * Sq;
    const float scl = 0.08838834764831845f;
    s2(kvHin, Wth + DD, Wtl + DD, Bv + 512, nullptr, nullptr, P.kv2h, P.kv2l,
       Mkv, 512, 512, 512, 512, 512, 0, 0,0,0,0,0,0,0, 1,1, 1.f, 0, g_sD);
    s2(kvHin, Wth + 2*DD, Wtl + 2*DD, Bv + 2*512, nullptr, P.kv2f, nullptr, nullptr,
       Mkv, 512, 512, 512, 512, 512, 0, 0,0,0,0,0,0,0, 1,1, 1.f, 0, g_sD);
    dim3 tb(32, 8);
    tconv<<<dim3(4, Skv/32, 16), tb, 0, g_sD>>>(P.kv2f, P.vt2h, P.vt2l,
                                                 512, (long)Skv * 512, 128, 4,
                                                 Skv, (long)128 * Skv);
    s2(qH, P.kv2h, P.kv2l, nullptr, nullptr, P.sc2, nullptr, nullptr,
       Sq, Skv, 128, 512, 512, Skv, 0,
       (long)Sq*512, 128, (long)Skv*512, 128, (long)4*Sq*Skv, (long)Sq*Skv, 0,
       4, 4, scl, 0, g_sD);
    softmax_kernel<<<16 * Sq, 128, 0, g_sD>>>(P.sc2, Skv, P.p2h);
    s2(P.p2h, P.vt2h, P.vt2l, nullptr, nullptr, nullptr, P.ao2h, nullptr,
       Sq, 128, Skv, Skv, Skv, 512, 0,
       (long)4*Sq*Skv, (long)Sq*Skv, (long)4*128*Skv, (long)128*Skv,
       (long)Sq*512, 128, 0,
       4, 4, 1.f, 0, g_sD);
    s2(P.ao2h, Wth + 3*DD, Wtl + 3*DD, Bv + 3*512, resid, outF, nullptr, nullptr,
       Mq, 512, 512, 512, 512, 512, 512, 0,0,0,0,0,0,0, 1,1, 1.f, 0, g_sD);
}

extern "C" void kernel_launch(void* const* d_in, const int* in_sizes, int n_in,
                              void* d_out, int out_size) {
    const float* h_bytes   = (const float*)d_in[0];
    const int*   b0        = (const int*)d_in[1];
    const int*   b1        = (const int*)d_in[2];
    const int*   b2        = (const int*)d_in[3];
    const float* mlp_ln_g  = (const float*)d_in[4];
    const float* mlp_ln_b  = (const float*)d_in[5];
    const float* mlp_w1    = (const float*)d_in[6];
    const float* mlp_b1    = (const float*)d_in[7];
    const float* mlp_w2    = (const float*)d_in[8];
    const float* mlp_b2    = (const float*)d_in[9];
    const float* ca_w      = (const float*)d_in[10];
    const float* ca_b      = (const float*)d_in[11];
    const float* ca_ln_g   = (const float*)d_in[12];
    const float* ca_ln_b   = (const float*)d_in[13];

    ensure_streams();
    g_evi = 0;

    Ptrs P;
    cudaGetSymbolAddress((void**)&P.seg0, g_seg0);
    cudaGetSymbolAddress((void**)&P.seg1, g_seg1);
    cudaGetSymbolAddress((void**)&P.seg2, g_seg2);
    cudaGetSymbolAddress((void**)&P.kvf, g_kv);
    cudaGetSymbolAddress((void**)&P.scb, g_sc);
    cudaGetSymbolAddress((void**)&P.kv2f, g_kv2);
    cudaGetSymbolAddress((void**)&P.sc2, g_sc2);
    cudaGetSymbolAddress((void**)&P.st, g_starts);
    cudaGetSymbolAddress((void**)&P.lnh, g_lnh);
    cudaGetSymbolAddress((void**)&P.ln2h, g_ln2h);
    cudaGetSymbolAddress((void**)&P.hh, g_hh);
    cudaGetSymbolAddress((void**)&P.q2h, g_q2h);
    cudaGetSymbolAddress((void**)&P.q3h, g_q3h);
    cudaGetSymbolAddress((void**)&P.q4h, g_q4h);
    cudaGetSymbolAddress((void**)&P.q5h, g_q5h);
    cudaGetSymbolAddress((void**)&P.kvh, g_kvh);   cudaGetSymbolAddress((void**)&P.kvl, g_kvl);
    cudaGetSymbolAddress((void**)&P.ph, g_ph);
    cudaGetSymbolAddress((void**)&P.aoh, g_aoh);
    cudaGetSymbolAddress((void**)&P.kv2h, g_kv2h); cudaGetSymbolAddress((void**)&P.kv2l, g_kv2l);
    cudaGetSymbolAddress((void**)&P.vt2h, g_vt2h); cudaGetSymbolAddress((void**)&P.vt2l, g_vt2l);
    cudaGetSymbolAddress((void**)&P.p2h, g_p2h);
    cudaGetSymbolAddress((void**)&P.ao2h, g_ao2h);
    cudaGetSymbolAddress((void**)&P.s1h, g_s1h);
    cudaGetSymbolAddress((void**)&P.s2h, g_s2h);
    cudaGetSymbolAddress((void**)&P.fuh, g_fuh);
    cudaGetSymbolAddress((void**)&P.vth, g_vth);   cudaGetSymbolAddress((void**)&P.vtl, g_vtl);
    cudaGetSymbolAddress((void**)&P.w1th, g_w1th); cudaGetSymbolAddress((void**)&P.w1tl, g_w1tl);
    cudaGetSymbolAddress((void**)&P.w2th, g_w2th); cudaGetSymbolAddress((void**)&P.w2tl, g_w2tl);
    cudaGetSymbolAddress((void**)&P.cath, g_cath); cudaGetSymbolAddress((void**)&P.catl, g_catl);

    int* st0 = P.st;
    int* st1 = P.st + 4 * 1025;
    int* st2 = st1 + 4 * 257;

    float* OUT0 = (float*)d_out;
    float* OUT1 = OUT0 + (long)4 * 1024 * 512;
    float* OUT2 = OUT1 + (long)4 * 256 * 512;

    const hf* WhI1 = P.cath + (long)8 * DD;
    const hf* WlI1 = P.catl + (long)8 * DD;
    const float* BvI1 = ca_b + (long)8 * 512;

    dim3 tb(32, 8);
    forkTo(g_sB);
    tconv<<<dim3(32, 16, 3), tb, 0, g_sB>>>(mlp_w1, P.w1th, P.w1tl, 1024, 512*1024, 0, 1, 512, 524288);
    tconv<<<dim3(16, 32, 3), tb, 0, g_sB>>>(mlp_w2, P.w2th, P.w2tl, 512, 524288, 0, 1, 1024, 524288);
    tconv<<<dim3(16, 16, 16), tb, 0, g_sB>>>(ca_w, P.cath, P.catl, 512, 262144, 0, 1, 512, 262144);

    starts_all<<<12, 256>>>(b0, b1, b2, P.st);

    // ---- level 0 ----
    pool_ln_kernel<<<dim3(1024, 4), 128>>>(h_bytes, P.seg0, P.lnh, st0,
                                           8192, 1024, mlp_ln_g, mlp_ln_b);
    joinFrom(g_sB);
    s2(P.lnh, P.w1th, P.w1tl, mlp_b1, nullptr, nullptr, P.hh, nullptr,
       4096, 1024, 512, 512, 512, 1024, 0, 0,0,0,0,0,0,0, 1,1, 1.f, 1, 0);
    s2(P.hh, P.w2th, P.w2tl, mlp_b2, P.seg0, P.seg0, nullptr, nullptr,
       4096, 512, 1024, 1024, 1024, 512, 512, 0,0,0,0,0,0,0, 1,1, 1.f, 0, 0);
    qchain(P, P.seg0, 4096, ca_ln_g, ca_ln_b, P.cath, P.catl, ca_b, P.q2h);

    // ---- level 1 ----
    pool_ln_kernel<<<dim3(256, 4), 128>>>(P.seg0, P.seg1, P.lnh, st1,
                                          1024, 256, mlp_ln_g + 512, mlp_ln_b + 512);
    s2(P.lnh, P.w1th + 524288, P.w1tl + 524288, mlp_b1 + 1024, nullptr,
       nullptr, P.hh, nullptr,
       1024, 1024, 512, 512, 512, 1024, 0, 0,0,0,0,0,0,0, 1,1, 1.f, 1, 0);
    s2(P.hh, P.w2th + 524288, P.w2tl + 524288, mlp_b2 + 512, P.seg1,
       P.seg1, nullptr, nullptr,
       1024, 512, 1024, 1024, 1024, 512, 512, 0,0,0,0,0,0,0, 1,1, 1.f, 0, 0);
    qchain(P, P.seg1, 1024, ca_ln_g + 1024, ca_ln_b + 1024, WhI1, WlI1, BvI1, P.q5h);

    // ---- level 2 ----
    pool_ln_kernel<<<dim3(64, 4), 128>>>(P.seg1, P.seg2, P.lnh, st2,
                                         256, 64, mlp_ln_g + 1024, mlp_ln_b + 1024);
    s2(P.lnh, P.w1th + 2*524288, P.w1tl + 2*524288, mlp_b1 + 2048, nullptr,
       nullptr, P.hh, nullptr,
       256, 1024, 512, 512, 512, 1024, 0, 0,0,0,0,0,0,0, 1,1, 1.f, 1, 0);
    s2(P.hh, P.w2th + 2*524288, P.w2tl + 2*524288, mlp_b2 + 1024, P.seg2,
       P.seg2, P.s2h, nullptr,
       256, 512, 1024, 1024, 1024, 512, 512, 0,0,0,0,0,0,0, 1,1, 1.f, 0, 0);
    qchain(P, P.seg2, 256, ca_ln_g + 1536, ca_ln_b + 1536, WhI1 + 4*DD, WlI1 + 4*DD,
           BvI1 + 4*512, P.q4h);
    cudaEventRecord(g_eq4, g_sC);

    // ---- i1 bu (critical): fu1 -> seg1 (+s1h) ----
    mha_pq(P, P.q5h, 256, P.s2h, 64, WhI1, WlI1, BvI1, P.seg1, P.seg1, P.s1h);
    // i0-td Q chain (needs seg1 = fu1)
    qchain(P, P.seg1, 1024, ca_ln_g + 512, ca_ln_b + 512, P.cath + 4*DD, P.catl + 4*DD,
           ca_b + 4*512, P.q3h);

    // ---- i1 td on stream D, concurrent with i0 bu ----
    forkTo(g_sD);
    cudaStreamWaitEvent(g_sD, g_eq4, 0);
    mha_onD(P, P.q4h, 64, P.s1h, 256, WhI1 + 4*DD, WlI1 + 4*DD, BvI1 + 4*512,
            P.seg2, OUT2);

    // ---- i0 bu: fu0 -> OUT0 (+fuh) ----
    mha_pq(P, P.q2h, 1024, P.s1h, 256, P.cath, P.catl, ca_b, P.seg0, OUT0, P.fuh);
    // ---- i0 td: cu0 -> OUT1 ----
    mha_pq(P, P.q3h, 256, P.fuh, 1024, P.cath + 4*DD, P.catl + 4*DD, ca_b + 4*512,
           P.seg1, OUT1, nullptr);

    joinFrom(g_sD);
}

// round 17
// speedup vs baseline: 1.1240x; 1.0277x over previous
#include <cuda_runtime.h>
#include <cuda_fp16.h>
#include <math.h>
#include <stdint.h>

#define Dm 512
#define DD (512*512)
typedef __half hf;

// ---------------- scratch (device globals; no allocation) ----------------
__device__ __align__(16) float g_seg0[4*1024*512];
__device__ __align__(16) float g_seg1[4*256*512];
__device__ __align__(16) float g_seg2[4*64*512];
__device__ __align__(16) float g_kv  [4096*1024];
__device__ __align__(16) float g_sc  [16*1024*256];
__device__ int g_starts[4*1025 + 4*257 + 4*65];

// activations: single fp16
__device__ __align__(16) hf g_lnh[4096*512];
__device__ __align__(16) hf g_ln2h[4096*512];
__device__ __align__(16) hf g_hh [4096*1024];
__device__ __align__(16) hf g_q2h[4096*512];
__device__ __align__(16) hf g_q3h[1024*512];
__device__ __align__(16) hf g_q4h[256*512];
__device__ __align__(16) hf g_q5h[1024*512];
__device__ __align__(16) hf g_ph [16*1024*256];
__device__ __align__(16) hf g_aoh[4096*512];
__device__ __align__(16) hf g_s1h[4*256*512];
__device__ __align__(16) hf g_s2h[4*64*512];
__device__ __align__(16) hf g_fuh[4096*512];
// B-side operands: fp16 hi/lo pairs
__device__ __align__(16) hf g_kvh[4096*512], g_kvl[4096*512];
__device__ __align__(16) hf g_vth[16*128*1024], g_vtl[16*128*1024];
__device__ __align__(16) hf g_w1th[3*1024*512], g_w1tl[3*1024*512];
__device__ __align__(16) hf g_w2th[3*512*1024], g_w2tl[3*512*1024];
__device__ __align__(16) hf g_cath[16*512*512], g_catl[16*512*512];

// private scratch for the concurrent small MHA (i1-td: Sq=64, Skv=256)
__device__ __align__(16) float g_kv2[1024*512];
__device__ __align__(16) float g_sc2[16*64*256];
__device__ __align__(16) hf g_kv2h[1024*512], g_kv2l[1024*512];
__device__ __align__(16) hf g_vt2h[16*128*256], g_vt2l[16*128*256];
__device__ __align__(16) hf g_p2h[16*64*256];
__device__ __align__(16) hf g_ao2h[256*512];

__device__ __forceinline__ void f16hl(float x, hf& h, hf& l) {
    h = __float2half_rn(x);
    l = __float2half_rn(x - __half2float(h));
}

// ---------------- fused boundary scans (R12 parallel scan, verified 12.5us) ---
__global__ void starts_all(const int* __restrict__ b0, const int* __restrict__ b1,
                           const int* __restrict__ b2, int* __restrict__ stall) {
    const int T = 256;
    int lvl = blockIdx.x >> 2, batch = blockIdx.x & 3;
    const int* bsrc; int L, nseg; int* st;
    if (lvl == 0)      { bsrc = b0; L = 8192; nseg = 1024; st = stall + batch * 1025; }
    else if (lvl == 1) { bsrc = b1; L = 1024; nseg = 256;  st = stall + 4*1025 + batch * 257; }
    else               { bsrc = b2; L = 256;  nseg = 64;   st = stall + 4*1025 + 4*257 + batch * 65; }
    int t = threadIdx.x;
    const int* bi = bsrc + (long)batch * L;
    for (int i = t; i <= nseg; i += T) st[i] = L;
    int chunk = (L + T - 1) / T;
    int beg = t * chunk, end = beg + chunk; if (end > L) end = L;
    int cnt = 0;
    for (int i = beg; i < end; i++) cnt += (bi[i] != 0);
    __shared__ int sc[T];
    sc[t] = cnt;
    __syncthreads();
    for (int d = 1; d < T; d <<= 1) {
        int v = (t >= d) ? sc[t - d] : 0;
        __syncthreads();
        sc[t] += v;
        __syncthreads();
    }
    int off = sc[t] - cnt;
    for (int i = beg; i < end; i++)
        if (bi[i]) { if (off < nseg) st[off] = i; off++; }
    __syncthreads();
    if (t == 0) st[nseg] = L;
}

// ---------------- fused segment mean pool + LN (fp16 emit) --------------------
__global__ void pool_ln_kernel(const float* __restrict__ x, float* __restrict__ seg,
                               hf* __restrict__ yh,
                               const int* __restrict__ starts, int Lin, int nseg,
                               const float* __restrict__ g, const float* __restrict__ bt) {
    int b = blockIdx.y, s0 = blockIdx.x;
    const int* st = starts + (long)b * (nseg + 1);
    int beg = st[s0], end = st[s0 + 1];
    int t = threadIdx.x;
    float4 v = make_float4(0.f, 0.f, 0.f, 0.f);
    for (int r = beg; r < end; r++) {
        float4 u = ((const float4*)(x + ((long)b * Lin + r) * Dm))[t];
        v.x += u.x; v.y += u.y; v.z += u.z; v.w += u.w;
    }
    int c = end - beg; if (c < 1) c = 1;
    float invc = 1.0f / (float)c;
    v.x *= invc; v.y *= invc; v.z *= invc; v.w *= invc;
    long row = (long)b * nseg + s0;
    ((float4*)(seg + row * Dm))[t] = v;
    float s  = v.x + v.y + v.z + v.w;
    float sq = v.x * v.x + v.y * v.y + v.z * v.z + v.w * v.w;
    __shared__ float sh[8];
    __shared__ float stats[2];
    for (int o = 16; o; o >>= 1) {
        s  += __shfl_xor_sync(0xffffffffu, s, o);
        sq += __shfl_xor_sync(0xffffffffu, sq, o);
    }
    int w = t >> 5;
    if ((t & 31) == 0) { sh[w] = s; sh[4 + w] = sq; }
    __syncthreads();
    if (t == 0) {
        float S = sh[0] + sh[1] + sh[2] + sh[3];
        float Q = sh[4] + sh[5] + sh[6] + sh[7];
        float mu = S * (1.0f / 512.0f);
        float var = Q * (1.0f / 512.0f) - mu * mu;
        stats[0] = mu; stats[1] = rsqrtf(var + 1e-5f);
    }
    __syncthreads();
    float mu = stats[0], inv = stats[1];
    float4 gg = ((const float4*)g)[t];
    float4 bb = ((const float4*)bt)[t];
    hf h[4];
    h[0] = __float2half_rn((v.x - mu) * inv * gg.x + bb.x);
    h[1] = __float2half_rn((v.y - mu) * inv * gg.y + bb.y);
    h[2] = __float2half_rn((v.z - mu) * inv * gg.z + bb.z);
    h[3] = __float2half_rn((v.w - mu) * inv * gg.w + bb.w);
    *(uint2*)(yh + row * Dm + t * 4) = *(uint2*)h;
}

// ---------------- layernorm (fp16 emit) ----------------------------------------
__global__ void ln_kernel(const float* __restrict__ x, hf* __restrict__ yh,
                          const float* __restrict__ g, const float* __restrict__ bt) {
    long row = blockIdx.x;
    int t = threadIdx.x;
    float4 v = ((const float4*)(x + row * Dm))[t];
    float s  = v.x + v.y + v.z + v.w;
    float sq = v.x * v.x + v.y * v.y + v.z * v.z + v.w * v.w;
    __shared__ float sh[8];
    __shared__ float stats[2];
    for (int o = 16; o; o >>= 1) {
        s  += __shfl_xor_sync(0xffffffffu, s, o);
        sq += __shfl_xor_sync(0xffffffffu, sq, o);
    }
    int w = t >> 5;
    if ((t & 31) == 0) { sh[w] = s; sh[4 + w] = sq; }
    __syncthreads();
    if (t == 0) {
        float S = sh[0] + sh[1] + sh[2] + sh[3];
        float Q = sh[4] + sh[5] + sh[6] + sh[7];
        float mu = S * (1.0f / 512.0f);
        float var = Q * (1.0f / 512.0f) - mu * mu;
        stats[0] = mu; stats[1] = rsqrtf(var + 1e-5f);
    }
    __syncthreads();
    float mu = stats[0], inv = stats[1];
    float4 gg = ((const float4*)g)[t];
    float4 bb = ((const float4*)bt)[t];
    hf h[4];
    h[0] = __float2half_rn((v.x - mu) * inv * gg.x + bb.x);
    h[1] = __float2half_rn((v.y - mu) * inv * gg.y + bb.y);
    h[2] = __float2half_rn((v.z - mu) * inv * gg.z + bb.z);
    h[3] = __float2half_rn((v.w - mu) * inv * gg.w + bb.w);
    *(uint2*)(yh + row * Dm + t * 4) = *(uint2*)h;
}

// ---------------- registerized row softmax (fp16 emit) -------------------------
__global__ void softmax_kernel(const float* __restrict__ sc, int L,
                               hf* __restrict__ ph) {
    long row = blockIdx.x;
    const float* r = sc + row * (long)L;
    int t = threadIdx.x;
    __shared__ float wr[4];
    __shared__ float bval;
    float v[8];
    int cnt = 0;
    float mx = -3.4e38f;
    for (int i = t; i < L; i += 128) {
        v[cnt] = r[i];
        mx = fmaxf(mx, v[cnt]);
        cnt++;
    }
    for (int o = 16; o; o >>= 1) mx = fmaxf(mx, __shfl_xor_sync(0xffffffffu, mx, o));
    if ((t & 31) == 0) wr[t >> 5] = mx;
    __syncthreads();
    if (t == 0) bval = fmaxf(fmaxf(wr[0], wr[1]), fmaxf(wr[2], wr[3]));
    __syncthreads();
    mx = bval;
    float s = 0.f;
    #pragma unroll 8
    for (int j = 0; j < cnt; j++) { v[j] = expf(v[j] - mx); s += v[j]; }
    for (int o = 16; o; o >>= 1) s += __shfl_xor_sync(0xffffffffu, s, o);
    if ((t & 31) == 0) wr[t >> 5] = s;
    __syncthreads();
    if (t == 0) bval = wr[0] + wr[1] + wr[2] + wr[3];
    __syncthreads();
    float inv = 1.0f / bval;
    cnt = 0;
    for (int i = t; i < L; i += 128)
        ph[row * (long)L + i] = __float2half_rn(v[cnt++] * inv);
}

// ---------------- transpose + convert (fp16 hi/lo pair) -----------------------
__global__ void tconv(const float* __restrict__ in, hf* __restrict__ oh,
                      hf* __restrict__ ol, int ldin, long szb, long szh, int nH,
                      int ldout, long szout) {
    int z = blockIdx.z, bb = z / nH, hh = z % nH;
    const float* src = in + bb * szb + hh * szh;
    oh += (long)z * szout; ol += (long)z * szout;
    __shared__ float tbuf[32][33];
    int r0 = blockIdx.y * 32, c0 = blockIdx.x * 32;
    for (int i = threadIdx.y; i < 32; i += 8)
        tbuf[i][threadIdx.x] = src[(long)(r0 + i) * ldin + c0 + threadIdx.x];
    __syncthreads();
    for (int i = threadIdx.y; i < 32; i += 8) {
        float x = tbuf[threadIdx.x][i];
        hf h, l; f16hl(x, h, l);
        long o = (long)(c0 + i) * ldout + r0 + threadIdx.x;
        oh[o] = h; ol[o] = l;
    }
}

// ---------------- mma / ldmatrix helpers --------------------------------------
__device__ __forceinline__ void mma16816(float* c, const unsigned* a, const unsigned* b) {
    asm volatile("mma.sync.aligned.m16n8k16.row.col.f32.f16.f16.f32 "
        "{%0,%1,%2,%3}, {%4,%5,%6,%7}, {%8,%9}, {%0,%1,%2,%3};"
        : "+f"(c[0]), "+f"(c[1]), "+f"(c[2]), "+f"(c[3])
        : "r"(a[0]), "r"(a[1]), "r"(a[2]), "r"(a[3]), "r"(b[0]), "r"(b[1]));
}
__device__ __forceinline__ void ldsm4(unsigned& r0, unsigned& r1, unsigned& r2,
                                      unsigned& r3, unsigned a) {
    asm volatile("ldmatrix.sync.aligned.m8n8.x4.shared.b16 {%0,%1,%2,%3}, [%4];"
        : "=r"(r0), "=r"(r1), "=r"(r2), "=r"(r3) : "r"(a));
}

__device__ __forceinline__ void epi_emit(
    float x0, float x1, int m, int n, long ldc, long ldres,
    const float* bias, const float* res, float* Cf, hf* Chi, hf* Clo, int doGelu) {
    if (bias) { x0 += bias[n]; x1 += bias[n + 1]; }
    if (doGelu) {
        x0 = 0.5f * x0 * (1.0f + erff(x0 * 0.70710678118654752f));
        x1 = 0.5f * x1 * (1.0f + erff(x1 * 0.70710678118654752f));
    }
    if (res) {
        float2 rv = *(const float2*)(res + (long)m * ldres + n);
        x0 += rv.x; x1 += rv.y;
    }
    long o = (long)m * ldc + n;
    if (Cf) *(float2*)(Cf + o) = make_float2(x0, x1);
    if (Chi) {
        if (Clo) {
            hf h0, l0, h1, l1;
            f16hl(x0, h0, l0); f16hl(x1, h1, l1);
            __half2 hv; hv.x = h0; hv.y = h1;
            __half2 lv; lv.x = l0; lv.y = l1;
            *(__half2*)(Chi + o) = hv;
            *(__half2*)(Clo + o) = lv;
        } else {
            __half2 hv; hv.x = __float2half_rn(x0); hv.y = __float2half_rn(x1);
            *(__half2*)(Chi + o) = hv;
        }
    }
}

// ---------------- 128x128 fp16 split-2 GEMM (A single, B hi/lo) ---------------
__global__ void __launch_bounds__(256) gemm_s2(
    const hf* __restrict__ A,
    const hf* __restrict__ Bh, const hf* __restrict__ Bl,
    const float* __restrict__ bias, const float* __restrict__ res,
    float* Cf, hf* Chi, hf* Clo,
    int K, int lda, int ldb, int ldc, int ldres,
    long sAb, long sAhh, long sBb, long sBhh, long sCb, long sChh, long sRb,
    int nH, float alpha, int doGelu)
{
    int z = blockIdx.z, bb = z / nH, hh = z - bb * nH;
    A += bb * sAb + hh * sAhh;
    Bh += bb * sBb + hh * sBhh; Bl += bb * sBb + hh * sBhh;
    long coff = bb * sCb + hh * sChh;
    if (Cf) Cf += coff;
    if (Chi) { Chi += coff; if (Clo) Clo += coff; }
    if (res) res += bb * sRb;

    __shared__ __align__(16) unsigned char smem[36864];

    int tid = threadIdx.x;
    int lrow = tid >> 1, lch = tid & 1;
    int m0 = blockIdx.y * 128, n0 = blockIdx.x * 128;

    const hf* pA  = A  + (long)(m0 + lrow) * lda + lch * 8;
    const hf* pBh = Bh + (long)(n0 + lrow) * ldb + lch * 8;
    const hf* pBl = Bl + (long)(n0 + lrow) * ldb + lch * 8;

    int soff = lrow * 48 + lch * 16;
    uint4 vA = *(const uint4*)pA;
    uint4 vBh = *(const uint4*)pBh, vBl = *(const uint4*)pBl;
    *(uint4*)(smem + soff)                 = vA;
    *(uint4*)(smem + 12288 + soff)         = vBh;
    *(uint4*)(smem + 12288 + 6144 + soff)  = vBl;
    __syncthreads();

    int wid = tid >> 5, lane = tid & 31;
    int wm = wid & 3, wn = wid >> 2;
    unsigned sbase = (unsigned)__cvta_generic_to_shared(smem);
    int lrel = ((lane & 7) + ((lane >> 3) & 1) * 8) * 48 + (lane >> 4) * 16;
    unsigned aBase = sbase + (unsigned)(wm * 32 * 48 + lrel);
    unsigned bBase = sbase + 12288u + (unsigned)(wn * 64 * 48 + lrel);

    float acc[2][8][4];
    #pragma unroll
    for (int i = 0; i < 2; i++)
        #pragma unroll
        for (int j = 0; j < 8; j++)
            #pragma unroll
            for (int kq = 0; kq < 4; kq++) acc[i][j][kq] = 0.f;

    int nk = K >> 4;
    for (int t = 0; t < nk; t++) {
        int cur = t & 1;
        if (t + 1 < nk) {
            int ko = (t + 1) << 4;
            vA = *(const uint4*)(pA + ko);
            vBh = *(const uint4*)(pBh + ko); vBl = *(const uint4*)(pBl + ko);
        }
        unsigned aAddr = aBase + cur * 6144u;
        unsigned bH = bBase + cur * 12288u, bL = bH + 6144u;
        unsigned a[2][4];
        ldsm4(a[0][0], a[0][1], a[0][2], a[0][3], aAddr);
        ldsm4(a[1][0], a[1][1], a[1][2], a[1][3], aAddr + 768u);
        #pragma unroll
        for (int p = 0; p < 4; p++) {
            unsigned h0, h1, h2, h3, l0, l1, l2, l3;
            ldsm4(h0, h1, h2, h3, bH + p * 768u);
            ldsm4(l0, l1, l2, l3, bL + p * 768u);
            unsigned bEv[2] = {h0, h2}, bOd[2] = {h1, h3};
            unsigned cEv[2] = {l0, l2}, cOd[2] = {l1, l3};
            #pragma unroll
            for (int mf = 0; mf < 2; mf++) {
                mma16816(acc[mf][2*p],     a[mf], bEv);
                mma16816(acc[mf][2*p],     a[mf], cEv);
                mma16816(acc[mf][2*p + 1], a[mf], bOd);
                mma16816(acc[mf][2*p + 1], a[mf], cOd);
            }
        }
        if (t + 1 < nk) {
            unsigned nb = (cur ^ 1);
            *(uint4*)(smem + nb * 6144 + soff)                  = vA;
            *(uint4*)(smem + 12288 + nb * 12288 + soff)         = vBh;
            *(uint4*)(smem + 12288 + nb * 12288 + 6144 + soff)  = vBl;
        }
        __syncthreads();
    }

    int g = lane >> 2, c = lane & 3;
    #pragma unroll
    for (int mf = 0; mf < 2; mf++)
        #pragma unroll
        for (int half = 0; half < 2; half++) {
            int m = m0 + wm * 32 + mf * 16 + g + half * 8;
            #pragma unroll
            for (int nf = 0; nf < 8; nf++) {
                int n = n0 + wn * 64 + nf * 8 + 2 * c;
                epi_emit(alpha * acc[mf][nf][half*2], alpha * acc[mf][nf][half*2+1],
                         m, n, ldc, ldres, bias, res, Cf, Chi, Clo, doGelu);
            }
        }
}

// ---------------- 64x64 fp16 split-2 GEMM (scalar-LDS) ------------------------
#define SKW6 72
__global__ void __launch_bounds__(128) gemm_s2s(
    const hf* __restrict__ A,
    const hf* __restrict__ Bh, const hf* __restrict__ Bl,
    const float* __restrict__ bias, const float* __restrict__ res,
    float* Cf, hf* Chi, hf* Clo,
    int K, int lda, int ldb, int ldc, int ldres,
    long sAb, long sAhh, long sBb, long sBhh, long sCb, long sChh, long sRb,
    int nH, float alpha, int doGelu)
{
    int z = blockIdx.z, bb = z / nH, hh = z - bb * nH;
    A += bb * sAb + hh * sAhh;
    Bh += bb * sBb + hh * sBhh; Bl += bb * sBb + hh * sBhh;
    long coff = bb * sCb + hh * sChh;
    if (Cf) Cf += coff;
    if (Chi) { Chi += coff; if (Clo) Clo += coff; }
    if (res) res += bb * sRb;

    __shared__ unsigned sA[2][8 * SKW6];
    __shared__ unsigned sBh[2][8 * SKW6], sBl[2][8 * SKW6];

    int tid = threadIdx.x;
    int row = tid & 63, kh = tid >> 6;
    int m0 = blockIdx.y * 64, n0 = blockIdx.x * 64;

    const hf* pA  = A  + (long)(m0 + row) * lda + kh * 8;
    const hf* pBh = Bh + (long)(n0 + row) * ldb + kh * 8;
    const hf* pBl = Bl + (long)(n0 + row) * ldb + kh * 8;

    uint4 vA = *(const uint4*)pA;
    uint4 vBh = *(const uint4*)pBh, vBl = *(const uint4*)pBl;
    int sb = kh * 4 * SKW6 + row;
    sA[0][sb] = vA.x; sA[0][sb + SKW6] = vA.y; sA[0][sb + 2*SKW6] = vA.z; sA[0][sb + 3*SKW6] = vA.w;
    sBh[0][sb] = vBh.x; sBh[0][sb + SKW6] = vBh.y; sBh[0][sb + 2*SKW6] = vBh.z; sBh[0][sb + 3*SKW6] = vBh.w;
    sBl[0][sb] = vBl.x; sBl[0][sb + SKW6] = vBl.y; sBl[0][sb + 2*SKW6] = vBl.z; sBl[0][sb + 3*SKW6] = vBl.w;
    __syncthreads();

    int wid = tid >> 5, lane = tid & 31;
    int wm = wid & 1, wn = wid >> 1;
    int g = lane >> 2, c = lane & 3;
    int ar0 = wm * 32 + g, bc0 = wn * 32 + g;

    float acc[2][4][4];
    #pragma unroll
    for (int i = 0; i < 2; i++)
        #pragma unroll
        for (int j = 0; j < 4; j++)
            #pragma unroll
            for (int kq = 0; kq < 4; kq++) acc[i][j][kq] = 0.f;

    int nk = K >> 4;
    for (int t = 0; t < nk; t++) {
        int cur = t & 1;
        if (t + 1 < nk) {
            int ko = (t + 1) << 4;
            vA = *(const uint4*)(pA + ko);
            vBh = *(const uint4*)(pBh + ko); vBl = *(const uint4*)(pBl + ko);
        }
        unsigned a[2][4], bh[4][2], bl[4][2];
        const unsigned* SA = sA[cur];
        const unsigned* SB = sBh[cur]; const unsigned* SB2 = sBl[cur];
        #pragma unroll
        for (int mf = 0; mf < 2; mf++) {
            int r = ar0 + mf * 16;
            a[mf][0] = SA[c*SKW6 + r];      a[mf][1] = SA[c*SKW6 + r + 8];
            a[mf][2] = SA[(c+4)*SKW6 + r];  a[mf][3] = SA[(c+4)*SKW6 + r + 8];
        }
        #pragma unroll
        for (int nf = 0; nf < 4; nf++) {
            int cc = bc0 + nf * 8;
            bh[nf][0] = SB[c*SKW6 + cc];  bh[nf][1] = SB[(c+4)*SKW6 + cc];
            bl[nf][0] = SB2[c*SKW6 + cc]; bl[nf][1] = SB2[(c+4)*SKW6 + cc];
        }
        #pragma unroll
        for (int mf = 0; mf < 2; mf++)
            #pragma unroll
            for (int nf = 0; nf < 4; nf++) {
                mma16816(acc[mf][nf], a[mf], bh[nf]);
                mma16816(acc[mf][nf], a[mf], bl[nf]);
            }
        if (t + 1 < nk) {
            int nb = cur ^ 1;
            sA[nb][sb] = vA.x; sA[nb][sb + SKW6] = vA.y; sA[nb][sb + 2*SKW6] = vA.z; sA[nb][sb + 3*SKW6] = vA.w;
            sBh[nb][sb] = vBh.x; sBh[nb][sb + SKW6] = vBh.y; sBh[nb][sb + 2*SKW6] = vBh.z; sBh[nb][sb + 3*SKW6] = vBh.w;
            sBl[nb][sb] = vBl.x; sBl[nb][sb + SKW6] = vBl.y; sBl[nb][sb + 2*SKW6] = vBl.z; sBl[nb][sb + 3*SKW6] = vBl.w;
        }
        __syncthreads();
    }

    #pragma unroll
    for (int mf = 0; mf < 2; mf++)
        #pragma unroll
        for (int half = 0; half < 2; half++) {
            int m = m0 + wm * 32 + mf * 16 + g + half * 8;
            #pragma unroll
            for (int nf = 0; nf < 4; nf++) {
                int n = n0 + wn * 32 + nf * 8 + 2 * c;
                epi_emit(alpha * acc[mf][nf][half*2], alpha * acc[mf][nf][half*2+1],
                         m, n, ldc, ldres, bias, res, Cf, Chi, Clo, doGelu);
            }
        }
}

// ---------------- dispatch (stream-aware) --------------------------------------
static void s2(const hf* A, const hf* Bh, const hf* Bl,
               const float* bias, const float* res,
               float* Cf, hf* Chi, hf* Clo,
               int M, int N, int K, int lda, int ldb, int ldc, int ldres,
               long sAb, long sAh, long sBb, long sBh, long sCb, long sCh, long sRb,
               int nBat, int nH, float alpha, int doGelu, cudaStream_t st) {
    long nb128 = ((M % 128) || (N % 128)) ? 0 : (long)(M/128) * (N/128) * nBat * nH;
    if (nb128 >= 48) {
        dim3 gr(N / 128, M / 128, nBat * nH);
        gemm_s2<<<gr, 256, 0, st>>>(A, Bh, Bl, bias, res, Cf, Chi, Clo,
                                    K, lda, ldb, ldc, ldres,
                                    sAb, sAh, sBb, sBh, sCb, sCh, sRb, nH, alpha, doGelu);
    } else {
        dim3 gr(N / 64, M / 64, nBat * nH);
        gemm_s2s<<<gr, 128, 0, st>>>(A, Bh, Bl, bias, res, Cf, Chi, Clo,
                                     K, lda, ldb, ldc, ldres,
                                     sAb, sAh, sBb, sBh, sCb, sCh, sRb, nH, alpha, doGelu);
    }
}

// ---------------- stream fork/join (graph-capture-safe) ------------------------
static cudaStream_t g_sB = nullptr, g_sC = nullptr, g_sD = nullptr;
static cudaEvent_t g_ev[48];
static cudaEvent_t g_eq4 = nullptr;
static int g_evi = 0;

static void ensure_streams() {
    if (!g_sB) {
        cudaStreamCreateWithFlags(&g_sB, cudaStreamNonBlocking);
        cudaStreamCreateWithFlags(&g_sC, cudaStreamNonBlocking);
        cudaStreamCreateWithFlags(&g_sD, cudaStreamNonBlocking);
        for (int i = 0; i < 48; i++)
            cudaEventCreateWithFlags(&g_ev[i], cudaEventDisableTiming);
        cudaEventCreateWithFlags(&g_eq4, cudaEventDisableTiming);
    }
}
static void forkTo(cudaStream_t dst) {
    cudaEvent_t e = g_ev[g_evi++ % 48];
    cudaEventRecord(e, 0);
    cudaStreamWaitEvent(dst, e, 0);
}
static void joinFrom(cudaStream_t src) {
    cudaEvent_t e = g_ev[g_evi++ % 48];
    cudaEventRecord(e, src);
    cudaStreamWaitEvent(0, e, 0);
}
static void waitMark(cudaStream_t src) {
    cudaEvent_t e = g_ev[g_evi++ % 48];
    cudaEventRecord(e, src);
    cudaStreamWaitEvent(0, e, 0);
}

// ---------------- host pointers ------------------------------------------------
struct Ptrs {
    float *seg0, *seg1, *seg2, *kvf, *scb;
    float *kv2f, *sc2;
    hf *lnh, *ln2h, *hh;
    hf *q2h, *q3h, *q4h, *q5h;
    hf *kvh, *kvl, *ph, *aoh;
    hf *kv2h, *kv2l, *vt2h, *vt2l, *p2h, *ao2h;
    hf *s1h, *s2h, *fuh, *vth, *vtl;
    hf *w1th, *w1tl, *w2th, *w2tl, *cath, *catl;
    int *st;
};

// precompute LN + Q projection on stream C
static void qchain(Ptrs& P, const float* src, int rows,
                   const float* lg, const float* lb,
                   const hf* Wh, const hf* Wl, const float* Bv, hf* qh) {
    forkTo(g_sC);
    ln_kernel<<<rows, 128, 0, g_sC>>>(src, P.ln2h, lg, lb);
    s2(P.ln2h, Wh, Wl, Bv, nullptr, nullptr, qh, nullptr,
       rows, 512, 512, 512, 512, 512, 0, 0,0,0,0,0,0,0, 1,1, 1.f, 0, g_sC);
}

// MHA with precomputed Q, split K/V: scores start after K only
static void mha_pq(Ptrs& P, const hf* qH, int Sq,
                   const hf* kvHin, int Skv,
                   const hf* Wth, const hf* Wtl, const float* Bv,
                   const float* resid, float* outF, hf* outH) {
    int Mkv = 4 * Skv;
    int Mq = 4 * Sq;
    const float scl = 0.08838834764831845f;
    forkTo(g_sB);
    s2(kvHin, Wth + DD, Wtl + DD, Bv + 512, nullptr, nullptr, P.kvh, P.kvl,
       Mkv, 512, 512, 512, 512, 512, 0, 0,0,0,0,0,0,0, 1,1, 1.f, 0, g_sB);
    waitMark(g_sB);
    s2(kvHin, Wth + 2*DD, Wtl + 2*DD, Bv + 2*512, nullptr, P.kvf, nullptr, nullptr,
       Mkv, 512, 512, 512, 512, 512, 0, 0,0,0,0,0,0,0, 1,1, 1.f, 0, g_sB);
    dim3 tb(32, 8);
    tconv<<<dim3(4, Skv/32, 16), tb, 0, g_sB>>>(P.kvf, P.vth, P.vtl,
                                                 512, (long)Skv * 512, 128, 4,
                                                 Skv, (long)128 * Skv);
    joinFrom(g_sC);
    s2(qH, P.kvh, P.kvl, nullptr, nullptr, P.scb, nullptr, nullptr,
       Sq, Skv, 128, 512, 512, Skv, 0,
       (long)Sq*512, 128, (long)Skv*512, 128, (long)4*Sq*Skv, (long)Sq*Skv, 0,
       4, 4, scl, 0, 0);
    softmax_kernel<<<16 * Sq, 128>>>(P.scb, Skv, P.ph);
    joinFrom(g_sB);
    s2(P.ph, P.vth, P.vtl, nullptr, nullptr, nullptr, P.aoh, nullptr,
       Sq, 128, Skv, Skv, Skv, 512, 0,
       (long)4*Sq*Skv, (long)Sq*Skv, (long)4*128*Skv, (long)128*Skv,
       (long)Sq*512, 128, 0,
       4, 4, 1.f, 0, 0);
    s2(P.aoh, Wth + 3*DD, Wtl + 3*DD, Bv + 3*512, resid, outF, outH, nullptr,
       Mq, 512, 512, 512, 512, 512, 512, 0,0,0,0,0,0,0, 1,1, 1.f, 0, 0);
}

// small MHA fully on stream D with private buffers (Sq=64, Skv=256)
static void mha_onD(Ptrs& P, const hf* qH, int Sq,
                    const hf* kvHin, int Skv,
                    const hf* Wth, const hf* Wtl, const float* Bv,
                    const float* resid, float* outF) {
    int Mkv = 4 * Skv;
    int Mq = 4 * Sq;
    const float scl = 0.08838834764831845f;
    s2(kvHin, Wth + DD, Wtl + DD, Bv + 512, nullptr, nullptr, P.kv2h, P.kv2l,
       Mkv, 512, 512, 512, 512, 512, 0, 0,0,0,0,0,0,0, 1,1, 1.f, 0, g_sD);
    s2(kvHin, Wth + 2*DD, Wtl + 2*DD, Bv + 2*512, nullptr, P.kv2f, nullptr, nullptr,
       Mkv, 512, 512, 512, 512, 512, 0, 0,0,0,0,0,0,0, 1,1, 1.f, 0, g_sD);
    dim3 tb(32, 8);
    tconv<<<dim3(4, Skv/32, 16), tb, 0, g_sD>>>(P.kv2f, P.vt2h, P.vt2l,
                                                 512, (long)Skv * 512, 128, 4,
                                                 Skv, (long)128 * Skv);
    s2(qH, P.kv2h, P.kv2l, nullptr, nullptr, P.sc2, nullptr, nullptr,
       Sq, Skv, 128, 512, 512, Skv, 0,
       (long)Sq*512, 128, (long)Skv*512, 128, (long)4*Sq*Skv, (long)Sq*Skv, 0,
       4, 4, scl, 0, g_sD);
    softmax_kernel<<<16 * Sq, 128, 0, g_sD>>>(P.sc2, Skv, P.p2h);
    s2(P.p2h, P.vt2h, P.vt2l, nullptr, nullptr, nullptr, P.ao2h, nullptr,
       Sq, 128, Skv, Skv, Skv, 512, 0,
       (long)4*Sq*Skv, (long)Sq*Skv, (long)4*128*Skv, (long)128*Skv,
       (long)Sq*512, 128, 0,
       4, 4, 1.f, 0, g_sD);
    s2(P.ao2h, Wth + 3*DD, Wtl + 3*DD, Bv + 3*512, resid, outF, nullptr, nullptr,
       Mq, 512, 512, 512, 512, 512, 512, 0,0,0,0,0,0,0, 1,1, 1.f, 0, g_sD);
}

extern "C" void kernel_launch(void* const* d_in, const int* in_sizes, int n_in,
                              void* d_out, int out_size) {
    const float* h_bytes   = (const float*)d_in[0];
    const int*   b0        = (const int*)d_in[1];
    const int*   b1        = (const int*)d_in[2];
    const int*   b2        = (const int*)d_in[3];
    const float* mlp_ln_g  = (const float*)d_in[4];
    const float* mlp_ln_b  = (const float*)d_in[5];
    const float* mlp_w1    = (const float*)d_in[6];
    const float* mlp_b1    = (const float*)d_in[7];
    const float* mlp_w2    = (const float*)d_in[8];
    const float* mlp_b2    = (const float*)d_in[9];
    const float* ca_w      = (const float*)d_in[10];
    const float* ca_b      = (const float*)d_in[11];
    const float* ca_ln_g   = (const float*)d_in[12];
    const float* ca_ln_b   = (const float*)d_in[13];

    ensure_streams();
    g_evi = 0;

    Ptrs P;
    cudaGetSymbolAddress((void**)&P.seg0, g_seg0);
    cudaGetSymbolAddress((void**)&P.seg1, g_seg1);
    cudaGetSymbolAddress((void**)&P.seg2, g_seg2);
    cudaGetSymbolAddress((void**)&P.kvf, g_kv);
    cudaGetSymbolAddress((void**)&P.scb, g_sc);
    cudaGetSymbolAddress((void**)&P.kv2f, g_kv2);
    cudaGetSymbolAddress((void**)&P.sc2, g_sc2);
    cudaGetSymbolAddress((void**)&P.st, g_starts);
    cudaGetSymbolAddress((void**)&P.lnh, g_lnh);
    cudaGetSymbolAddress((void**)&P.ln2h, g_ln2h);
    cudaGetSymbolAddress((void**)&P.hh, g_hh);
    cudaGetSymbolAddress((void**)&P.q2h, g_q2h);
    cudaGetSymbolAddress((void**)&P.q3h, g_q3h);
    cudaGetSymbolAddress((void**)&P.q4h, g_q4h);
    cudaGetSymbolAddress((void**)&P.q5h, g_q5h);
    cudaGetSymbolAddress((void**)&P.kvh, g_kvh);   cudaGetSymbolAddress((void**)&P.kvl, g_kvl);
    cudaGetSymbolAddress((void**)&P.ph, g_ph);
    cudaGetSymbolAddress((void**)&P.aoh, g_aoh);
    cudaGetSymbolAddress((void**)&P.kv2h, g_kv2h); cudaGetSymbolAddress((void**)&P.kv2l, g_kv2l);
    cudaGetSymbolAddress((void**)&P.vt2h, g_vt2h); cudaGetSymbolAddress((void**)&P.vt2l, g_vt2l);
    cudaGetSymbolAddress((void**)&P.p2h, g_p2h);
    cudaGetSymbolAddress((void**)&P.ao2h, g_ao2h);
    cudaGetSymbolAddress((void**)&P.s1h, g_s1h);
    cudaGetSymbolAddress((void**)&P.s2h, g_s2h);
    cudaGetSymbolAddress((void**)&P.fuh, g_fuh);
    cudaGetSymbolAddress((void**)&P.vth, g_vth);   cudaGetSymbolAddress((void**)&P.vtl, g_vtl);
    cudaGetSymbolAddress((void**)&P.w1th, g_w1th); cudaGetSymbolAddress((void**)&P.w1tl, g_w1tl);
    cudaGetSymbolAddress((void**)&P.w2th, g_w2th); cudaGetSymbolAddress((void**)&P.w2tl, g_w2tl);
    cudaGetSymbolAddress((void**)&P.cath, g_cath); cudaGetSymbolAddress((void**)&P.catl, g_catl);

    int* st0 = P.st;
    int* st1 = P.st + 4 * 1025;
    int* st2 = st1 + 4 * 257;

    float* OUT0 = (float*)d_out;
    float* OUT1 = OUT0 + (long)4 * 1024 * 512;
    float* OUT2 = OUT1 + (long)4 * 256 * 512;

    const hf* WhI1 = P.cath + (long)8 * DD;
    const hf* WlI1 = P.catl + (long)8 * DD;
    const float* BvI1 = ca_b + (long)8 * 512;

    dim3 tb(32, 8);
    forkTo(g_sB);
    tconv<<<dim3(32, 16, 3), tb, 0, g_sB>>>(mlp_w1, P.w1th, P.w1tl, 1024, 512*1024, 0, 1, 512, 524288);
    tconv<<<dim3(16, 32, 3), tb, 0, g_sB>>>(mlp_w2, P.w2th, P.w2tl, 512, 524288, 0, 1, 1024, 524288);
    tconv<<<dim3(16, 16, 16), tb, 0, g_sB>>>(ca_w, P.cath, P.catl, 512, 262144, 0, 1, 512, 262144);

    starts_all<<<12, 256>>>(b0, b1, b2, P.st);

    // ---- level 0 ----
    pool_ln_kernel<<<dim3(1024, 4), 128>>>(h_bytes, P.seg0, P.lnh, st0,
                                           8192, 1024, mlp_ln_g, mlp_ln_b);
    joinFrom(g_sB);
    s2(P.lnh, P.w1th, P.w1tl, mlp_b1, nullptr, nullptr, P.hh, nullptr,
       4096, 1024, 512, 512, 512, 1024, 0, 0,0,0,0,0,0,0, 1,1, 1.f, 1, 0);
    s2(P.hh, P.w2th, P.w2tl, mlp_b2, P.seg0, P.seg0, nullptr, nullptr,
       4096, 512, 1024, 1024, 1024, 512, 512, 0,0,0,0,0,0,0, 1,1, 1.f, 0, 0);
    qchain(P, P.seg0, 4096, ca_ln_g, ca_ln_b, P.cath, P.catl, ca_b, P.q2h);

    // ---- level 1 ----
    pool_ln_kernel<<<dim3(256, 4), 128>>>(P.seg0, P.seg1, P.lnh, st1,
                                          1024, 256, mlp_ln_g + 512, mlp_ln_b + 512);
    s2(P.lnh, P.w1th + 524288, P.w1tl + 524288, mlp_b1 + 1024, nullptr,
       nullptr, P.hh, nullptr,
       1024, 1024, 512, 512, 512, 1024, 0, 0,0,0,0,0,0,0, 1,1, 1.f, 1, 0);
    s2(P.hh, P.w2th + 524288, P.w2tl + 524288, mlp_b2 + 512, P.seg1,
       P.seg1, nullptr, nullptr,
       1024, 512, 1024, 1024, 1024, 512, 512, 0,0,0,0,0,0,0, 1,1, 1.f, 0, 0);
    qchain(P, P.seg1, 1024, ca_ln_g + 1024, ca_ln_b + 1024, WhI1, WlI1, BvI1, P.q5h);

    // ---- level 2 ----
    pool_ln_kernel<<<dim3(64, 4), 128>>>(P.seg1, P.seg2, P.lnh, st2,
                                         256, 64, mlp_ln_g + 1024, mlp_ln_b + 1024);
    s2(P.lnh, P.w1th + 2*524288, P.w1tl + 2*524288, mlp_b1 + 2048, nullptr,
       nullptr, P.hh, nullptr,
       256, 1024, 512, 512, 512, 1024, 0, 0,0,0,0,0,0,0, 1,1, 1.f, 1, 0);
    s2(P.hh, P.w2th + 2*524288, P.w2tl + 2*524288, mlp_b2 + 1024, P.seg2,
       P.seg2, P.s2h, nullptr,
       256, 512, 1024, 1024, 1024, 512, 512, 0,0,0,0,0,0,0, 1,1, 1.f, 0, 0);
    qchain(P, P.seg2, 256, ca_ln_g + 1536, ca_ln_b + 1536, WhI1 + 4*DD, WlI1 + 4*DD,
           BvI1 + 4*512, P.q4h);
    cudaEventRecord(g_eq4, g_sC);

    // ---- i1 bu (critical): fu1 -> seg1 (+s1h) ----
    mha_pq(P, P.q5h, 256, P.s2h, 64, WhI1, WlI1, BvI1, P.seg1, P.seg1, P.s1h);
    // i0-td Q chain (needs seg1 = fu1)
    qchain(P, P.seg1, 1024, ca_ln_g + 512, ca_ln_b + 512, P.cath + 4*DD, P.catl + 4*DD,
           ca_b + 4*512, P.q3h);

    // ---- i1 td on stream D, concurrent with i0 bu ----
    forkTo(g_sD);
    cudaStreamWaitEvent(g_sD, g_eq4, 0);
    mha_onD(P, P.q4h, 64, P.s1h, 256, WhI1 + 4*DD, WlI1 + 4*DD, BvI1 + 4*512,
            P.seg2, OUT2);

    // ---- i0 bu: fu0 -> OUT0 (+fuh) ----
    mha_pq(P, P.q2h, 1024, P.s1h, 256, P.cath, P.catl, ca_b, P.seg0, OUT0, P.fuh);
    // ---- i0 td: cu0 -> OUT1 ----
    mha_pq(P, P.q3h, 256, P.fuh, 1024, P.cath + 4*DD, P.catl + 4*DD, ca_b + 4*512,
           P.seg1, OUT1, nullptr);

    joinFrom(g_sD);
}